// round 1
// baseline (speedup 1.0000x reference)
#include <cuda_runtime.h>
#include <math.h>

#define K 4
#define N 4096
#define D 256
#define S 32
#define MAXDEG 512
#define ETA 0.5f
#define COEFF 0.03125f   // S/(N*EPS^2) = 32/(4096*0.25)

// ---------------- scratch (__device__ globals; no allocation allowed) ----------------
__device__ float g_Zt[K * N * S];      // Z transposed: [k][n][s]
__device__ float g_MZt[K * N * S];     // M^-1 Z transposed: [k][n][s]
__device__ float g_Minv[K * S * S];
__device__ float g_O[K * N * S];       // attention output: [k][n][s]
__device__ float g_Hagg[N * D];
__device__ float g_Ut[K * S * D];      // U transposed: [k][s][d]
__device__ int   g_col[(size_t)N * MAXDEG];
__device__ int   g_deg[N];
__device__ float g_w[K];
__device__ float g_partials[N];

__device__ __forceinline__ float warpSum(float v) {
    v += __shfl_xor_sync(0xffffffffu, v, 16);
    v += __shfl_xor_sync(0xffffffffu, v, 8);
    v += __shfl_xor_sync(0xffffffffu, v, 4);
    v += __shfl_xor_sync(0xffffffffu, v, 2);
    v += __shfl_xor_sync(0xffffffffu, v, 1);
    return v;
}

// ---------------- w = softmax(hop_weights) ----------------
__global__ void k_w(const float* hw) {
    if (threadIdx.x == 0) {
        float m = hw[0];
        for (int i = 1; i < K; i++) m = fmaxf(m, hw[i]);
        float e[K], s = 0.f;
        for (int i = 0; i < K; i++) { e[i] = expf(hw[i] - m); s += e[i]; }
        for (int i = 0; i < K; i++) g_w[i] = e[i] / s;
    }
}

// ---------------- Ut[k][s][d] = U[k][d][s] ----------------
__global__ void k_transU(const float* U) {
    int idx = blockIdx.x * blockDim.x + threadIdx.x;
    if (idx >= K * D * S) return;
    int k = idx / (D * S);
    int rem = idx % (D * S);
    int d = rem / S;
    int s = rem % S;
    g_Ut[(k * S + s) * D + d] = U[idx];
}

// ---------------- CSR build from adjacency (warp per row, ordered compaction) ----------------
__global__ void k_csr(const float* __restrict__ A) {
    int n = blockIdx.x * 8 + (threadIdx.x >> 5);
    int lane = threadIdx.x & 31;
    const float* row = A + (size_t)n * N;
    int cnt = 0;
    for (int base = 0; base < N; base += 32) {
        float a = row[base + lane];
        unsigned mask = __ballot_sync(0xffffffffu, a != 0.0f);
        if (a != 0.0f) {
            int pos = cnt + __popc(mask & ((1u << lane) - 1u));
            if (pos < MAXDEG) g_col[(size_t)n * MAXDEG + pos] = base + lane;
        }
        cnt += __popc(mask);
    }
    if (lane == 0) g_deg[n] = min(cnt, MAXDEG);
}

// ---------------- Zt[k][n][s] = sum_d U[k][d][s] * hops[k][n][d] ----------------
__global__ void k_Z(const float* __restrict__ hops, const float* __restrict__ U) {
    int s = threadIdx.x;                       // 0..31
    int n = blockIdx.x * 8 + threadIdx.y;      // 8 rows per block
    int k = blockIdx.y;
    const float* hrow = hops + ((size_t)k * N + n) * D;
    const float* Uk = U + (size_t)k * D * S;
    float acc = 0.f;
#pragma unroll 8
    for (int d = 0; d < D; d++) acc += Uk[d * S + s] * hrow[d];
    g_Zt[((size_t)k * N + n) * S + s] = acc;
}

// ---------------- Gram + (I + coeff*G)^-1 via Gauss-Jordan (one block per k) ----------------
__global__ void k_gram_inv(void) {
    int k = blockIdx.x;
    int s = threadIdx.x >> 5, t = threadIdx.x & 31;
    const float* Z = g_Zt + (size_t)k * N * S;
    float g = 0.f;
#pragma unroll 4
    for (int n = 0; n < N; n++) g += Z[n * S + s] * Z[n * S + t];

    __shared__ float aug[32][66];
    aug[s][t] = (s == t ? 1.0f : 0.0f) + COEFF * g;
    aug[s][32 + t] = (s == t ? 1.0f : 0.0f);
    __syncthreads();

    int r0 = threadIdx.x >> 6, c0 = threadIdx.x & 63;
    int tid2 = threadIdx.x + 1024;
    int r1 = tid2 >> 6, c1 = tid2 & 63;
    for (int p = 0; p < 32; p++) {
        float pv = aug[p][p];
        float inv = 1.0f / pv;
        float f0 = aug[r0][p], pr0 = aug[p][c0];
        float f1 = aug[r1][p], pr1 = aug[p][c1];
        __syncthreads();
        if (r0 == p) aug[p][c0] = pr0 * inv;
        else         aug[r0][c0] -= f0 * inv * pr0;
        if (r1 == p) aug[p][c1] = pr1 * inv;
        else         aug[r1][c1] -= f1 * inv * pr1;
        __syncthreads();
    }
    g_Minv[k * S * S + s * S + t] = aug[s][32 + t];
}

// ---------------- MZt[k][n][s] = sum_t Minv[k][s][t] * Zt[k][n][t] ----------------
__global__ void k_MZ(void) {
    __shared__ float Minv_sh[32 * 32];
    __shared__ float zsh[8][32];
    int tid = threadIdx.y * 32 + threadIdx.x;
    int k = blockIdx.y;
    for (int i = tid; i < 1024; i += 256) Minv_sh[i] = g_Minv[k * 1024 + i];
    int n = blockIdx.x * 8 + threadIdx.y;
    zsh[threadIdx.y][threadIdx.x] = g_Zt[((size_t)k * N + n) * S + threadIdx.x];
    __syncthreads();
    int s = threadIdx.x;
    float acc = 0.f;
#pragma unroll
    for (int t = 0; t < 32; t++) acc += Minv_sh[s * 32 + t] * zsh[threadIdx.y][t];
    g_MZt[((size_t)k * N + n) * S + s] = acc;
}

// ---------------- sparse masked attention: warp per (n,k), online softmax ----------------
__global__ void k_attn(void) {
    int gwarp = blockIdx.x * 8 + (threadIdx.x >> 5);
    int lane = threadIdx.x & 31;
    int k = gwarp / N;
    int n = gwarp % N;
    float q = g_Zt[((size_t)k * N + n) * S + lane];
    const float* MZ = g_MZt + (size_t)k * N * S;
    const int* cols = g_col + (size_t)n * MAXDEG;
    int dn = g_deg[n];
    float m = -1e30f, l = 0.f, acc = 0.f;
    for (int c = 0; c < dn; c++) {
        int j = cols[c];
        float v = MZ[(size_t)j * S + lane];
        float sc = warpSum(q * v);
        float mn = fmaxf(m, sc);
        float corr = expf(m - mn);
        float p = expf(sc - mn);
        l = l * corr + p;
        acc = acc * corr + p * v;
        m = mn;
    }
    g_O[((size_t)k * N + n) * S + lane] = acc / l;
}

// ---------------- Hagg[n][d] = sum_k w[k] * sum_s Ut[k][s][d] * O[k][n][s] ----------------
__global__ void k_Hagg(void) {
    __shared__ float Osh[K * 32];
    __shared__ float wsh[K];
    int n = blockIdx.x, d = threadIdx.x;
    if (d < K * 32) Osh[d] = g_O[(size_t)(d >> 5) * N * S + (size_t)n * S + (d & 31)];
    if (d < K) wsh[d] = g_w[d];
    __syncthreads();
    float h = 0.f;
#pragma unroll
    for (int k = 0; k < K; k++) {
        float a = 0.f;
#pragma unroll
        for (int s = 0; s < S; s++)
            a += g_Ut[((size_t)k * S + s) * D + d] * Osh[k * 32 + s];
        h += wsh[k] * a;
    }
    g_Hagg[(size_t)n * D + d] = h;
}

// ---------------- H_out = softthresh(hops0 + ETA*(Hagg - lambda*L@Hagg)) ----------------
__global__ void k_Hout(const float* __restrict__ hops,
                       const float* __restrict__ threshold,
                       const float* __restrict__ lambda_lap,
                       float* __restrict__ out) {
    int n = blockIdx.x, d = threadIdx.x;
    __shared__ int csh[MAXDEG];
    int dn = g_deg[n];
    for (int i = d; i < dn; i += 256) csh[i] = g_col[(size_t)n * MAXDEG + i];
    __syncthreads();
    float hagg = g_Hagg[(size_t)n * D + d];
    float lh = (float)dn * hagg;
    for (int c = 0; c < dn; c++) lh -= g_Hagg[(size_t)csh[c] * D + d];
    float lam = lambda_lap[0];
    float hh = hops[(size_t)n * D + d] + ETA * (hagg - lam * lh);
    float ab = fabsf(hh) - threshold[d];
    float o = (ab > 0.f) ? copysignf(ab, hh) : 0.f;
    out[(size_t)n * D + d] = o;
}

// ---------------- per-row partials of lap_smooth = sum H_out * (L @ H_out) ----------------
__global__ void k_lap(const float* __restrict__ Hout) {
    int n = blockIdx.x, d = threadIdx.x;
    __shared__ int csh[MAXDEG];
    __shared__ float red[256];
    int dn = g_deg[n];
    for (int i = d; i < dn; i += 256) csh[i] = g_col[(size_t)n * MAXDEG + i];
    __syncthreads();
    float ho = Hout[(size_t)n * D + d];
    float lh = (float)dn * ho;
    for (int c = 0; c < dn; c++) lh -= Hout[(size_t)csh[c] * D + d];
    red[d] = ho * lh;
    __syncthreads();
    for (int off = 128; off > 0; off >>= 1) {
        if (d < off) red[d] += red[d + off];
        __syncthreads();
    }
    if (d == 0) g_partials[n] = red[0];
}

// ---------------- final: lap_smooth reduce + orth_loss + scalars (deterministic) ----------------
__global__ void k_final(const float* __restrict__ U, float* __restrict__ out, int out_size) {
    __shared__ float red[1024];
    int tid = threadIdx.x;

    // lap_smooth: fixed-order reduction
    float v = g_partials[tid] + g_partials[tid + 1024] +
              g_partials[tid + 2048] + g_partials[tid + 3072];
    red[tid] = v;
    __syncthreads();
    for (int off = 512; off > 0; off >>= 1) {
        if (tid < off) red[tid] += red[tid + off];
        __syncthreads();
    }
    float lap_smooth = red[0];
    __syncthreads();

    // orth_loss: thread handles (s,t), loops pairs (k<=l)
    int s = tid >> 5, t = tid & 31;
    float o = 0.f;
    for (int k = 0; k < K; k++) {
        for (int l = k; l < K; l++) {
            float c = 0.f;
#pragma unroll 4
            for (int d = 0; d < D; d++)
                c += U[((size_t)k * D + d) * S + s] * U[((size_t)l * D + d) * S + t];
            if (k == l && s == t) c -= 1.0f;
            o += c * c;
        }
    }
    red[tid] = o;
    __syncthreads();
    for (int off = 512; off > 0; off >>= 1) {
        if (tid < off) red[tid] += red[tid + off];
        __syncthreads();
    }
    if (tid == 0) {
        int base = N * D;
        if (base < out_size) out[base] = red[0];            // orth_loss
        if (base + 1 < out_size) out[base + 1] = lap_smooth; // lap_smooth
        for (int i = 0; i < K; i++)
            if (base + 2 + i < out_size) out[base + 2 + i] = g_w[i]; // w
    }
}

// ---------------- launch ----------------
extern "C" void kernel_launch(void* const* d_in, const int* in_sizes, int n_in,
                              void* d_out, int out_size) {
    const float* hops      = (const float*)d_in[0]; // (K,N,D)
    const float* adj       = (const float*)d_in[1]; // (N,N)
    // d_in[2] = L (unused; reconstructed from adj)
    const float* U         = (const float*)d_in[3]; // (K,D,S)
    const float* hw        = (const float*)d_in[4]; // (K,)
    const float* threshold = (const float*)d_in[5]; // (D,)
    const float* lam       = (const float*)d_in[6]; // scalar
    float* out = (float*)d_out;

    k_w<<<1, 32>>>(hw);
    k_transU<<<(K * D * S + 255) / 256, 256>>>(U);
    k_csr<<<N / 8, 256>>>(adj);
    {
        dim3 b(32, 8), g(N / 8, K);
        k_Z<<<g, b>>>(hops, U);
    }
    k_gram_inv<<<K, 1024>>>();
    {
        dim3 b(32, 8), g(N / 8, K);
        k_MZ<<<g, b>>>();
    }
    k_attn<<<(K * N) / 8, 256>>>();
    k_Hagg<<<N, 256>>>();
    k_Hout<<<N, 256>>>(hops, threshold, lam, out);
    k_lap<<<N, 256>>>(out);
    k_final<<<1, 1024>>>(U, out, out_size);
}

// round 2
// speedup vs baseline: 2.9356x; 2.9356x over previous
#include <cuda_runtime.h>
#include <math.h>

#define K 4
#define N 4096
#define D 256
#define S 32
#define MAXDEG 512
#define ETA 0.5f
#define COEFF 0.03125f   // S/(N*EPS^2)

// ---------------- scratch ----------------
__device__ float g_Zt[K * N * S];      // [k][n][s]
__device__ float g_MZt[K * N * S];
__device__ float g_Minv[K * S * S];
__device__ float g_O[K * N * S];
__device__ float g_Hagg[N * D];
__device__ float g_Wc[K * S * D];      // w_k * U[k]^T : [k*S+s][d]
__device__ float g_gramP[K * 64 * S * S];
__device__ int   g_col[(size_t)N * MAXDEG];
__device__ int   g_deg[N];
__device__ float g_w[K];
__device__ float g_partials[N];
__device__ float g_orth[10];

__device__ __forceinline__ float warpSum(float v) {
    v += __shfl_xor_sync(0xffffffffu, v, 16);
    v += __shfl_xor_sync(0xffffffffu, v, 8);
    v += __shfl_xor_sync(0xffffffffu, v, 4);
    v += __shfl_xor_sync(0xffffffffu, v, 2);
    v += __shfl_xor_sync(0xffffffffu, v, 1);
    return v;
}

// ---------------- w = softmax(hop_weights) ----------------
__global__ void k_w(const float* hw) {
    if (threadIdx.x == 0) {
        float m = hw[0];
        for (int i = 1; i < K; i++) m = fmaxf(m, hw[i]);
        float e[K], s = 0.f;
        for (int i = 0; i < K; i++) { e[i] = expf(hw[i] - m); s += e[i]; }
        for (int i = 0; i < K; i++) g_w[i] = e[i] / s;
    }
}

// ---------------- Wc[k*S+s][d] = w_k * U[k][d][s] ----------------
__global__ void k_prepW(const float* __restrict__ U, const float* __restrict__ hw) {
    int idx = blockIdx.x * blockDim.x + threadIdx.x;
    if (idx >= K * D * S) return;
    int k = idx / (D * S);
    int rem = idx % (D * S);
    int d = rem / S;
    int s = rem % S;
    float m = fmaxf(fmaxf(hw[0], hw[1]), fmaxf(hw[2], hw[3]));
    float e0 = expf(hw[0] - m), e1 = expf(hw[1] - m), e2 = expf(hw[2] - m), e3 = expf(hw[3] - m);
    float sum = e0 + e1 + e2 + e3;
    float wk = (k == 0 ? e0 : k == 1 ? e1 : k == 2 ? e2 : e3) / sum;
    g_Wc[(k * S + s) * D + d] = wk * U[idx];
}

// ---------------- CSR build (warp per row, ordered compaction) ----------------
__global__ void k_csr(const float* __restrict__ A) {
    int n = blockIdx.x * 8 + (threadIdx.x >> 5);
    int lane = threadIdx.x & 31;
    const float* row = A + (size_t)n * N;
    int cnt = 0;
    for (int base = 0; base < N; base += 32) {
        float a = row[base + lane];
        unsigned mask = __ballot_sync(0xffffffffu, a != 0.0f);
        if (a != 0.0f) {
            int pos = cnt + __popc(mask & ((1u << lane) - 1u));
            if (pos < MAXDEG) g_col[(size_t)n * MAXDEG + pos] = base + lane;
        }
        cnt += __popc(mask);
    }
    if (lane == 0) g_deg[n] = min(cnt, MAXDEG);
}

// ---------------- Z = hops[k] @ U[k] : tiled GEMM (32n x 32s, tile d=32) ----------------
__global__ void k_Z(const float* __restrict__ hops, const float* __restrict__ U) {
    __shared__ float hs[32][33];   // [n][d]
    __shared__ float us[32][33];   // [d][s]
    int k = blockIdx.y;
    int n0 = blockIdx.x * 32;
    int lane = threadIdx.x & 31;
    int row = threadIdx.x >> 5;    // 0..7
    const float* Hb = hops + ((size_t)k * N + n0) * D;
    const float* Ub = U + (size_t)k * D * S;
    float acc[4] = {0.f, 0.f, 0.f, 0.f};
    for (int dc = 0; dc < D; dc += 32) {
#pragma unroll
        for (int i = 0; i < 4; i++) {
            int r = row + i * 8;
            hs[r][lane] = Hb[(size_t)r * D + dc + lane];
            us[r][lane] = Ub[(size_t)(dc + r) * S + lane];
        }
        __syncthreads();
#pragma unroll
        for (int dd = 0; dd < 32; dd++) {
            float u = us[dd][lane];
#pragma unroll
            for (int i = 0; i < 4; i++) acc[i] += hs[row * 4 + i][dd] * u;
        }
        __syncthreads();
    }
#pragma unroll
    for (int i = 0; i < 4; i++)
        g_Zt[((size_t)k * N + n0 + row * 4 + i) * S + lane] = acc[i];
}

// ---------------- partial Grams: 64 chunks of 64 rows per k ----------------
__global__ void k_gramP(void) {
    __shared__ float zs[64 * 32];
    int k = blockIdx.y, chunk = blockIdx.x;
    const float* Z = g_Zt + ((size_t)k * N + chunk * 64) * S;
    for (int i = threadIdx.x; i < 64 * 32; i += 1024) zs[i] = Z[i];
    __syncthreads();
    int s = threadIdx.x >> 5, t = threadIdx.x & 31;
    float g = 0.f;
#pragma unroll 8
    for (int n = 0; n < 64; n++) g += zs[n * 32 + s] * zs[n * 32 + t];
    g_gramP[(((size_t)k * 64 + chunk) * S + s) * S + t] = g;
}

// ---------------- reduce partials + (I + coeff*G)^-1 Gauss-Jordan ----------------
__global__ void k_inv(void) {
    int k = blockIdx.x;
    int s = threadIdx.x >> 5, t = threadIdx.x & 31;
    float g = 0.f;
    for (int c = 0; c < 64; c++)
        g += g_gramP[(((size_t)k * 64 + c) * S + s) * S + t];

    __shared__ float aug[32][66];
    aug[s][t] = (s == t ? 1.0f : 0.0f) + COEFF * g;
    aug[s][32 + t] = (s == t ? 1.0f : 0.0f);
    __syncthreads();

    int r0 = threadIdx.x >> 6, c0 = threadIdx.x & 63;
    int tid2 = threadIdx.x + 1024;
    int r1 = tid2 >> 6, c1 = tid2 & 63;
    for (int p = 0; p < 32; p++) {
        float inv = 1.0f / aug[p][p];
        float f0 = aug[r0][p], pr0 = aug[p][c0];
        float f1 = aug[r1][p], pr1 = aug[p][c1];
        __syncthreads();
        if (r0 == p) aug[p][c0] = pr0 * inv;
        else         aug[r0][c0] -= f0 * inv * pr0;
        if (r1 == p) aug[p][c1] = pr1 * inv;
        else         aug[r1][c1] -= f1 * inv * pr1;
        __syncthreads();
    }
    g_Minv[k * S * S + s * S + t] = aug[s][32 + t];
}

// ---------------- MZt[k][n][s] = Minv[k] @ Zt rows ----------------
__global__ void k_MZ(void) {
    __shared__ float Minv_sh[32 * 32];
    __shared__ float zsh[8][32];
    int tid = threadIdx.y * 32 + threadIdx.x;
    int k = blockIdx.y;
    for (int i = tid; i < 1024; i += 256) Minv_sh[i] = g_Minv[k * 1024 + i];
    int n = blockIdx.x * 8 + threadIdx.y;
    zsh[threadIdx.y][threadIdx.x] = g_Zt[((size_t)k * N + n) * S + threadIdx.x];
    __syncthreads();
    int s = threadIdx.x;
    float acc = 0.f;
#pragma unroll
    for (int t = 0; t < 32; t++) acc += Minv_sh[s * 32 + t] * zsh[threadIdx.y][t];
    g_MZt[((size_t)k * N + n) * S + s] = acc;
}

// ---------------- sparse masked attention: warp per (n,k), online softmax x4 ----------------
__global__ void k_attn(void) {
    int gwarp = blockIdx.x * 8 + (threadIdx.x >> 5);
    int lane = threadIdx.x & 31;
    int k = gwarp >> 12;
    int n = gwarp & (N - 1);
    float q = g_Zt[((size_t)k * N + n) * S + lane];
    const float* MZ = g_MZt + (size_t)k * N * S;
    const int* cols = g_col + (size_t)n * MAXDEG;
    int dn = g_deg[n];
    float m = -1e30f, l = 0.f, acc = 0.f;
    int c = 0;
    for (; c + 4 <= dn; c += 4) {
        int j0 = cols[c], j1 = cols[c + 1], j2 = cols[c + 2], j3 = cols[c + 3];
        float v0 = MZ[(size_t)j0 * S + lane];
        float v1 = MZ[(size_t)j1 * S + lane];
        float v2 = MZ[(size_t)j2 * S + lane];
        float v3 = MZ[(size_t)j3 * S + lane];
        float s0 = warpSum(q * v0);
        float s1 = warpSum(q * v1);
        float s2 = warpSum(q * v2);
        float s3 = warpSum(q * v3);
        float mloc = fmaxf(fmaxf(s0, s1), fmaxf(s2, s3));
        float mn = fmaxf(m, mloc);
        float corr = __expf(m - mn);
        float p0 = __expf(s0 - mn), p1 = __expf(s1 - mn);
        float p2 = __expf(s2 - mn), p3 = __expf(s3 - mn);
        l = l * corr + ((p0 + p1) + (p2 + p3));
        acc = acc * corr + ((p0 * v0 + p1 * v1) + (p2 * v2 + p3 * v3));
        m = mn;
    }
    for (; c < dn; c++) {
        int j = cols[c];
        float v = MZ[(size_t)j * S + lane];
        float sc = warpSum(q * v);
        float mn = fmaxf(m, sc);
        float corr = __expf(m - mn);
        float p = __expf(sc - mn);
        l = l * corr + p;
        acc = acc * corr + p * v;
        m = mn;
    }
    g_O[((size_t)k * N + n) * S + lane] = acc / l;
}

// ---------------- Hagg = O_cat (N x 4S) @ Wc (4S x D) : tiled GEMM ----------------
__global__ void k_Hagg(void) {
    __shared__ float as[32][33];   // [n][s]
    __shared__ float ws[32][33];   // [s][d]
    int n0 = blockIdx.x * 32, d0 = blockIdx.y * 32;
    int lane = threadIdx.x & 31;
    int row = threadIdx.x >> 5;
    float acc[4] = {0.f, 0.f, 0.f, 0.f};
    for (int k = 0; k < K; k++) {
#pragma unroll
        for (int i = 0; i < 4; i++) {
            int r = row + i * 8;
            as[r][lane] = g_O[((size_t)k * N + n0 + r) * S + lane];
            ws[r][lane] = g_Wc[((size_t)k * S + r) * D + d0 + lane];
        }
        __syncthreads();
#pragma unroll
        for (int dd = 0; dd < 32; dd++) {
            float wv = ws[dd][lane];
#pragma unroll
            for (int i = 0; i < 4; i++) acc[i] += as[row * 4 + i][dd] * wv;
        }
        __syncthreads();
    }
#pragma unroll
    for (int i = 0; i < 4; i++)
        g_Hagg[(size_t)(n0 + row * 4 + i) * D + d0 + lane] = acc[i];
}

// ---------------- H_out = softthresh(hops0 + ETA*(Hagg - lambda*L@Hagg)) (float4) ----------------
__global__ void k_Hout(const float* __restrict__ hops,
                       const float* __restrict__ threshold,
                       const float* __restrict__ lambda_lap,
                       float* __restrict__ out) {
    int n = blockIdx.x * 4 + (threadIdx.x >> 6);
    int t = threadIdx.x & 63;
    const float4* Hg = (const float4*)g_Hagg;
    const int* cols = g_col + (size_t)n * MAXDEG;
    int dn = g_deg[n];
    float4 hag = Hg[(size_t)n * 64 + t];
    float fd = (float)dn;
    float4 lh = make_float4(fd * hag.x, fd * hag.y, fd * hag.z, fd * hag.w);
    int c = 0;
    for (; c + 2 <= dn; c += 2) {
        float4 v0 = Hg[(size_t)cols[c] * 64 + t];
        float4 v1 = Hg[(size_t)cols[c + 1] * 64 + t];
        lh.x -= v0.x + v1.x; lh.y -= v0.y + v1.y;
        lh.z -= v0.z + v1.z; lh.w -= v0.w + v1.w;
    }
    if (c < dn) {
        float4 v = Hg[(size_t)cols[c] * 64 + t];
        lh.x -= v.x; lh.y -= v.y; lh.z -= v.z; lh.w -= v.w;
    }
    float lam = lambda_lap[0];
    float4 hp = ((const float4*)hops)[(size_t)n * 64 + t];
    float4 th = ((const float4*)threshold)[t];
    float4 o;
    {
        float hh = hp.x + ETA * (hag.x - lam * lh.x);
        float ab = fabsf(hh) - th.x; o.x = ab > 0.f ? copysignf(ab, hh) : 0.f;
        hh = hp.y + ETA * (hag.y - lam * lh.y);
        ab = fabsf(hh) - th.y; o.y = ab > 0.f ? copysignf(ab, hh) : 0.f;
        hh = hp.z + ETA * (hag.z - lam * lh.z);
        ab = fabsf(hh) - th.z; o.z = ab > 0.f ? copysignf(ab, hh) : 0.f;
        hh = hp.w + ETA * (hag.w - lam * lh.w);
        ab = fabsf(hh) - th.w; o.w = ab > 0.f ? copysignf(ab, hh) : 0.f;
    }
    ((float4*)out)[(size_t)n * 64 + t] = o;
}

// ---------------- per-row partials of lap_smooth (float4) ----------------
__global__ void k_lap(const float* __restrict__ Hout) {
    int n = blockIdx.x * 4 + (threadIdx.x >> 6);
    int t = threadIdx.x & 63;
    const float4* H = (const float4*)Hout;
    const int* cols = g_col + (size_t)n * MAXDEG;
    int dn = g_deg[n];
    float4 h = H[(size_t)n * 64 + t];
    float fd = (float)dn;
    float4 lh = make_float4(fd * h.x, fd * h.y, fd * h.z, fd * h.w);
    int c = 0;
    for (; c + 2 <= dn; c += 2) {
        float4 v0 = H[(size_t)cols[c] * 64 + t];
        float4 v1 = H[(size_t)cols[c + 1] * 64 + t];
        lh.x -= v0.x + v1.x; lh.y -= v0.y + v1.y;
        lh.z -= v0.z + v1.z; lh.w -= v0.w + v1.w;
    }
    if (c < dn) {
        float4 v = H[(size_t)cols[c] * 64 + t];
        lh.x -= v.x; lh.y -= v.y; lh.z -= v.z; lh.w -= v.w;
    }
    float dot = h.x * lh.x + h.y * lh.y + h.z * lh.z + h.w * lh.w;
    dot = warpSum(dot);
    __shared__ float sred[8];
    if ((threadIdx.x & 31) == 0) sred[threadIdx.x >> 5] = dot;
    __syncthreads();
    if (threadIdx.x < 4)
        g_partials[blockIdx.x * 4 + threadIdx.x] =
            sred[threadIdx.x * 2] + sred[threadIdx.x * 2 + 1];
}

// ---------------- orth partials: block per (k,l) pair ----------------
__global__ void k_orth(const float* __restrict__ U) {
    const int kk[10] = {0, 0, 0, 0, 1, 1, 1, 2, 2, 3};
    const int ll[10] = {0, 1, 2, 3, 1, 2, 3, 2, 3, 3};
    int p = blockIdx.x;
    int k = kk[p], l = ll[p];
    int s = threadIdx.x >> 5, t = threadIdx.x & 31;
    float c = 0.f;
#pragma unroll 8
    for (int d = 0; d < D; d++)
        c += U[((size_t)k * D + d) * S + s] * U[((size_t)l * D + d) * S + t];
    if (k == l && s == t) c -= 1.0f;
    float v = c * c;
    __shared__ float red[1024];
    red[threadIdx.x] = v;
    __syncthreads();
    for (int off = 512; off > 0; off >>= 1) {
        if (threadIdx.x < off) red[threadIdx.x] += red[threadIdx.x + off];
        __syncthreads();
    }
    if (threadIdx.x == 0) g_orth[p] = red[0];
}

// ---------------- final scalar assembly ----------------
__global__ void k_final(float* __restrict__ out, int out_size) {
    __shared__ float red[1024];
    int tid = threadIdx.x;
    float v = g_partials[tid] + g_partials[tid + 1024] +
              g_partials[tid + 2048] + g_partials[tid + 3072];
    red[tid] = v;
    __syncthreads();
    for (int off = 512; off > 0; off >>= 1) {
        if (tid < off) red[tid] += red[tid + off];
        __syncthreads();
    }
    if (tid == 0) {
        float orth = 0.f;
        for (int p = 0; p < 10; p++) orth += g_orth[p];
        int base = N * D;
        if (base < out_size) out[base] = orth;
        if (base + 1 < out_size) out[base + 1] = red[0];
        for (int i = 0; i < K; i++)
            if (base + 2 + i < out_size) out[base + 2 + i] = g_w[i];
    }
}

// ---------------- launch ----------------
extern "C" void kernel_launch(void* const* d_in, const int* in_sizes, int n_in,
                              void* d_out, int out_size) {
    const float* hops      = (const float*)d_in[0];
    const float* adj       = (const float*)d_in[1];
    const float* U         = (const float*)d_in[3];
    const float* hw        = (const float*)d_in[4];
    const float* threshold = (const float*)d_in[5];
    const float* lam       = (const float*)d_in[6];
    float* out = (float*)d_out;

    k_w<<<1, 32>>>(hw);
    k_prepW<<<(K * D * S + 255) / 256, 256>>>(U, hw);
    k_csr<<<N / 8, 256>>>(adj);
    {
        dim3 g(N / 32, K);
        k_Z<<<g, 256>>>(hops, U);
    }
    {
        dim3 g(64, K);
        k_gramP<<<g, 1024>>>();
    }
    k_inv<<<K, 1024>>>();
    {
        dim3 b(32, 8), g(N / 8, K);
        k_MZ<<<g, b>>>();
    }
    k_attn<<<(K * N) / 8, 256>>>();
    {
        dim3 g(N / 32, D / 32);
        k_Hagg<<<g, 256>>>();
    }
    k_Hout<<<N / 4, 256>>>(hops, threshold, lam, out);
    k_lap<<<N / 4, 256>>>(out);
    k_orth<<<10, 1024>>>(U);
    k_final<<<1, 1024>>>(out, out_size);
}

// round 3
// speedup vs baseline: 2.9881x; 1.0179x over previous
#include <cuda_runtime.h>
#include <math.h>

#define K 4
#define N 4096
#define D 256
#define S 32
#define MAXDEG 512
#define ETA 0.5f
#define COEFF 0.03125f   // S/(N*EPS^2)

// ---------------- scratch ----------------
__device__ float g_Zt[K * N * S];        // [k][n][s]
__device__ float g_MZt[K * N * S];       // [k][n][s]
__device__ float g_Minv[K * S * S];
__device__ float g_O[(size_t)N * (K * S)];   // O_cat: [n][k*S+s]  (512B rows)
__device__ float g_O2[(size_t)N * (K * S)];  // (I - lam*L) @ O_cat
__device__ float g_Wc[K * S * D];        // w_k * U[k]^T : [k*S+s][d]
__device__ float g_gramP[K * 64 * S * S];
__device__ int   g_col[(size_t)N * MAXDEG];
__device__ int   g_deg[N];
__device__ float g_w[K];
__device__ float g_partials[N];
__device__ float g_orth[10];

__device__ __forceinline__ float warpSum(float v) {
    v += __shfl_xor_sync(0xffffffffu, v, 16);
    v += __shfl_xor_sync(0xffffffffu, v, 8);
    v += __shfl_xor_sync(0xffffffffu, v, 4);
    v += __shfl_xor_sync(0xffffffffu, v, 2);
    v += __shfl_xor_sync(0xffffffffu, v, 1);
    return v;
}

// ---------------- w = softmax(hop_weights) ----------------
__global__ void k_w(const float* hw) {
    if (threadIdx.x == 0) {
        float m = hw[0];
        for (int i = 1; i < K; i++) m = fmaxf(m, hw[i]);
        float e[K], s = 0.f;
        for (int i = 0; i < K; i++) { e[i] = expf(hw[i] - m); s += e[i]; }
        for (int i = 0; i < K; i++) g_w[i] = e[i] / s;
    }
}

// ---------------- Wc[k*S+s][d] = w_k * U[k][d][s] ----------------
__global__ void k_prepW(const float* __restrict__ U, const float* __restrict__ hw) {
    int idx = blockIdx.x * blockDim.x + threadIdx.x;
    if (idx >= K * D * S) return;
    int k = idx / (D * S);
    int rem = idx % (D * S);
    int d = rem / S;
    int s = rem % S;
    float m = fmaxf(fmaxf(hw[0], hw[1]), fmaxf(hw[2], hw[3]));
    float e0 = expf(hw[0] - m), e1 = expf(hw[1] - m), e2 = expf(hw[2] - m), e3 = expf(hw[3] - m);
    float sum = e0 + e1 + e2 + e3;
    float wk = (k == 0 ? e0 : k == 1 ? e1 : k == 2 ? e2 : e3) / sum;
    g_Wc[(k * S + s) * D + d] = wk * U[idx];
}

// ---------------- CSR build (warp per row, unrolled x4 for MLP) ----------------
__global__ void k_csr(const float* __restrict__ A) {
    int n = blockIdx.x * 8 + (threadIdx.x >> 5);
    int lane = threadIdx.x & 31;
    const float* row = A + (size_t)n * N;
    int* dst = g_col + (size_t)n * MAXDEG;
    int cnt = 0;
    for (int base = 0; base < N; base += 128) {
        float a0 = row[base + lane];
        float a1 = row[base + 32 + lane];
        float a2 = row[base + 64 + lane];
        float a3 = row[base + 96 + lane];
        unsigned m0 = __ballot_sync(0xffffffffu, a0 != 0.0f);
        unsigned m1 = __ballot_sync(0xffffffffu, a1 != 0.0f);
        unsigned m2 = __ballot_sync(0xffffffffu, a2 != 0.0f);
        unsigned m3 = __ballot_sync(0xffffffffu, a3 != 0.0f);
        unsigned lm = (1u << lane) - 1u;
        if (a0 != 0.0f) dst[cnt + __popc(m0 & lm)] = base + lane;
        cnt += __popc(m0);
        if (a1 != 0.0f) dst[cnt + __popc(m1 & lm)] = base + 32 + lane;
        cnt += __popc(m1);
        if (a2 != 0.0f) dst[cnt + __popc(m2 & lm)] = base + 64 + lane;
        cnt += __popc(m2);
        if (a3 != 0.0f) dst[cnt + __popc(m3 & lm)] = base + 96 + lane;
        cnt += __popc(m3);
    }
    if (lane == 0) g_deg[n] = min(cnt, MAXDEG);
}

// ---------------- Z = hops[k] @ U[k] : register-tiled (64n x 32s, 2x4/thread) ----------------
__global__ void k_Z(const float* __restrict__ hops, const float* __restrict__ U) {
    __shared__ float hsT[32 * 66];  // [dd][r], stride 66
    __shared__ float us[32 * 36];   // [dd][s], stride 36
    int k = blockIdx.y;
    int n0 = blockIdx.x * 64;
    int tx = threadIdx.x;
    int ny = tx >> 3;               // 0..31 -> n pair
    int sx = (tx & 7) * 4;          // 0..28 step 4
    int dd = tx & 31;
    int r0 = tx >> 5;               // 0..7
    const float* Hb = hops + ((size_t)k * N + n0) * D;
    const float* Ub = U + (size_t)k * D * S;
    float a0x = 0.f, a0y = 0.f, a0z = 0.f, a0w = 0.f;
    float a1x = 0.f, a1y = 0.f, a1z = 0.f, a1w = 0.f;
    for (int dc = 0; dc < D; dc += 32) {
#pragma unroll
        for (int i = 0; i < 8; i++) {
            int r = r0 + i * 8;
            hsT[dd * 66 + r] = Hb[(size_t)r * D + dc + dd];
        }
#pragma unroll
        for (int i = 0; i < 4; i++) {
            int d2 = r0 + i * 8;
            us[d2 * 36 + dd] = Ub[(size_t)(dc + d2) * S + dd];
        }
        __syncthreads();
#pragma unroll
        for (int d = 0; d < 32; d++) {
            float2 h = *(const float2*)&hsT[d * 66 + ny * 2];
            float4 u = *(const float4*)&us[d * 36 + sx];
            a0x += h.x * u.x; a0y += h.x * u.y; a0z += h.x * u.z; a0w += h.x * u.w;
            a1x += h.y * u.x; a1y += h.y * u.y; a1z += h.y * u.z; a1w += h.y * u.w;
        }
        __syncthreads();
    }
    size_t base = ((size_t)k * N + n0 + ny * 2) * S + sx;
    *(float4*)&g_Zt[base] = make_float4(a0x, a0y, a0z, a0w);
    *(float4*)&g_Zt[base + S] = make_float4(a1x, a1y, a1z, a1w);
}

// ---------------- partial Grams: 64 chunks of 64 rows per k ----------------
__global__ void k_gramP(void) {
    __shared__ float zs[64 * 32];
    int k = blockIdx.y, chunk = blockIdx.x;
    const float* Z = g_Zt + ((size_t)k * N + chunk * 64) * S;
    for (int i = threadIdx.x; i < 64 * 32; i += 1024) zs[i] = Z[i];
    __syncthreads();
    int s = threadIdx.x >> 5, t = threadIdx.x & 31;
    float g = 0.f;
#pragma unroll 8
    for (int n = 0; n < 64; n++) g += zs[n * 32 + s] * zs[n * 32 + t];
    g_gramP[(((size_t)k * 64 + chunk) * S + s) * S + t] = g;
}

// ---------------- reduce partials + (I + coeff*G)^-1 Gauss-Jordan ----------------
__global__ void k_inv(void) {
    int k = blockIdx.x;
    int s = threadIdx.x >> 5, t = threadIdx.x & 31;
    float g = 0.f;
    for (int c = 0; c < 64; c++)
        g += g_gramP[(((size_t)k * 64 + c) * S + s) * S + t];

    __shared__ float aug[32][66];
    aug[s][t] = (s == t ? 1.0f : 0.0f) + COEFF * g;
    aug[s][32 + t] = (s == t ? 1.0f : 0.0f);
    __syncthreads();

    int r0 = threadIdx.x >> 6, c0 = threadIdx.x & 63;
    int tid2 = threadIdx.x + 1024;
    int r1 = tid2 >> 6, c1 = tid2 & 63;
    for (int p = 0; p < 32; p++) {
        float inv = 1.0f / aug[p][p];
        float f0 = aug[r0][p], pr0 = aug[p][c0];
        float f1 = aug[r1][p], pr1 = aug[p][c1];
        __syncthreads();
        if (r0 == p) aug[p][c0] = pr0 * inv;
        else         aug[r0][c0] -= f0 * inv * pr0;
        if (r1 == p) aug[p][c1] = pr1 * inv;
        else         aug[r1][c1] -= f1 * inv * pr1;
        __syncthreads();
    }
    g_Minv[k * S * S + s * S + t] = aug[s][32 + t];
}

// ---------------- MZt[k][n][s] = Minv[k] @ Zt rows ----------------
__global__ void k_MZ(void) {
    __shared__ float Minv_sh[32 * 32];
    __shared__ float zsh[8][32];
    int tid = threadIdx.y * 32 + threadIdx.x;
    int k = blockIdx.y;
    for (int i = tid; i < 1024; i += 256) Minv_sh[i] = g_Minv[k * 1024 + i];
    int n = blockIdx.x * 8 + threadIdx.y;
    zsh[threadIdx.y][threadIdx.x] = g_Zt[((size_t)k * N + n) * S + threadIdx.x];
    __syncthreads();
    int s = threadIdx.x;
    float acc = 0.f;
#pragma unroll
    for (int t = 0; t < 32; t++) acc += Minv_sh[s * 32 + t] * zsh[threadIdx.y][t];
    g_MZt[((size_t)k * N + n) * S + s] = acc;
}

// ---------------- sparse masked attention: warp per (n,k), online softmax x4 ----------------
__global__ void k_attn(void) {
    int gwarp = blockIdx.x * 8 + (threadIdx.x >> 5);
    int lane = threadIdx.x & 31;
    int k = gwarp >> 12;
    int n = gwarp & (N - 1);
    float q = g_Zt[((size_t)k * N + n) * S + lane];
    const float* MZ = g_MZt + (size_t)k * N * S;
    const int* cols = g_col + (size_t)n * MAXDEG;
    int dn = g_deg[n];
    float m = -1e30f, l = 0.f, acc = 0.f;
    int c = 0;
    for (; c + 4 <= dn; c += 4) {
        int j0 = cols[c], j1 = cols[c + 1], j2 = cols[c + 2], j3 = cols[c + 3];
        float v0 = MZ[(size_t)j0 * S + lane];
        float v1 = MZ[(size_t)j1 * S + lane];
        float v2 = MZ[(size_t)j2 * S + lane];
        float v3 = MZ[(size_t)j3 * S + lane];
        float s0 = warpSum(q * v0);
        float s1 = warpSum(q * v1);
        float s2 = warpSum(q * v2);
        float s3 = warpSum(q * v3);
        float mloc = fmaxf(fmaxf(s0, s1), fmaxf(s2, s3));
        float mn = fmaxf(m, mloc);
        float corr = __expf(m - mn);
        float p0 = __expf(s0 - mn), p1 = __expf(s1 - mn);
        float p2 = __expf(s2 - mn), p3 = __expf(s3 - mn);
        l = l * corr + ((p0 + p1) + (p2 + p3));
        acc = acc * corr + ((p0 * v0 + p1 * v1) + (p2 * v2 + p3 * v3));
        m = mn;
    }
    for (; c < dn; c++) {
        int j = cols[c];
        float v = MZ[(size_t)j * S + lane];
        float sc = warpSum(q * v);
        float mn = fmaxf(m, sc);
        float corr = __expf(m - mn);
        float p = __expf(sc - mn);
        l = l * corr + p;
        acc = acc * corr + p * v;
        m = mn;
    }
    g_O[(size_t)n * (K * S) + k * S + lane] = acc / l;
}

// ---------------- O2 = (I - lam*L) @ O_cat  (gather over 512B rows) ----------------
__global__ void k_lapO(const float* __restrict__ lambda_lap) {
    int n = blockIdx.x * 8 + (threadIdx.x >> 5);
    int lane = threadIdx.x & 31;
    const float4* O = (const float4*)g_O;
    const int* cols = g_col + (size_t)n * MAXDEG;
    int dn = g_deg[n];
    float4 o = O[(size_t)n * 32 + lane];
    float4 s = make_float4(0.f, 0.f, 0.f, 0.f);
    int c = 0;
    for (; c + 2 <= dn; c += 2) {
        float4 v0 = O[(size_t)cols[c] * 32 + lane];
        float4 v1 = O[(size_t)cols[c + 1] * 32 + lane];
        s.x += v0.x + v1.x; s.y += v0.y + v1.y;
        s.z += v0.z + v1.z; s.w += v0.w + v1.w;
    }
    if (c < dn) {
        float4 v = O[(size_t)cols[c] * 32 + lane];
        s.x += v.x; s.y += v.y; s.z += v.z; s.w += v.w;
    }
    float lam = lambda_lap[0];
    float fd = (float)dn;
    float4 r;
    r.x = o.x - lam * (fd * o.x - s.x);
    r.y = o.y - lam * (fd * o.y - s.y);
    r.z = o.z - lam * (fd * o.z - s.z);
    r.w = o.w - lam * (fd * o.w - s.w);
    ((float4*)g_O2)[(size_t)n * 32 + lane] = r;
}

// ---------------- H_out = softthresh(hops0 + ETA * O2 @ Wc) : tiled GEMM + epilogue ----------------
__global__ void k_HoutG(const float* __restrict__ hops,
                        const float* __restrict__ threshold,
                        float* __restrict__ out) {
    __shared__ float as[32][33];   // [n][c]
    __shared__ float ws[32][33];   // [c][d]
    int n0 = blockIdx.x * 32, d0 = blockIdx.y * 32;
    int lane = threadIdx.x & 31;
    int row = threadIdx.x >> 5;
    float acc[4] = {0.f, 0.f, 0.f, 0.f};
    for (int cc = 0; cc < K * S; cc += 32) {
#pragma unroll
        for (int i = 0; i < 4; i++) {
            int r = row + i * 8;
            as[r][lane] = g_O2[(size_t)(n0 + r) * (K * S) + cc + lane];
            ws[r][lane] = g_Wc[(size_t)(cc + r) * D + d0 + lane];
        }
        __syncthreads();
#pragma unroll
        for (int dd = 0; dd < 32; dd++) {
            float wv = ws[dd][lane];
#pragma unroll
            for (int i = 0; i < 4; i++) acc[i] += as[row * 4 + i][dd] * wv;
        }
        __syncthreads();
    }
    float th = threshold[d0 + lane];
#pragma unroll
    for (int i = 0; i < 4; i++) {
        int n = n0 + row * 4 + i;
        float hh = hops[(size_t)n * D + d0 + lane] + ETA * acc[i];
        float ab = fabsf(hh) - th;
        out[(size_t)n * D + d0 + lane] = (ab > 0.f) ? copysignf(ab, hh) : 0.f;
    }
}

// ---------------- lap_smooth partials: symmetric half-gather ----------------
// sum H(LH) = sum_n (deg_n - 1)|H_n|^2 - 2 * sum_n H_n . (sum_{j in N(n), j<n} H_j)
__global__ void k_lap(const float* __restrict__ Hout) {
    int n = blockIdx.x * 4 + (threadIdx.x >> 6);
    int t = threadIdx.x & 63;
    const float4* H = (const float4*)Hout;
    const int* cols = g_col + (size_t)n * MAXDEG;
    int dn = g_deg[n];
    float4 h = H[(size_t)n * 64 + t];
    float4 vs = make_float4(0.f, 0.f, 0.f, 0.f);
    for (int c = 0; c < dn; c++) {
        int j = cols[c];
        if (j >= n) break;
        float4 v = H[(size_t)j * 64 + t];
        vs.x += v.x; vs.y += v.y; vs.z += v.z; vs.w += v.w;
    }
    float fd = (float)dn - 1.0f;
    float dot = fd * (h.x * h.x + h.y * h.y + h.z * h.z + h.w * h.w)
              - 2.0f * (h.x * vs.x + h.y * vs.y + h.z * vs.z + h.w * vs.w);
    dot = warpSum(dot);
    __shared__ float sred[8];
    if ((threadIdx.x & 31) == 0) sred[threadIdx.x >> 5] = dot;
    __syncthreads();
    if (threadIdx.x < 4)
        g_partials[blockIdx.x * 4 + threadIdx.x] =
            sred[threadIdx.x * 2] + sred[threadIdx.x * 2 + 1];
}

// ---------------- orth partials: block per (k,l) pair, U staged in smem ----------------
__global__ void k_orth(const float* __restrict__ U) {
    const int kk[10] = {0, 0, 0, 0, 1, 1, 1, 2, 2, 3};
    const int ll[10] = {0, 1, 2, 3, 1, 2, 3, 2, 3, 3};
    int p = blockIdx.x;
    int k = kk[p], l = ll[p];
    int s = threadIdx.x >> 5, t = threadIdx.x & 31;
    __shared__ float uk[64 * 32];
    __shared__ float ul[64 * 32];
    float c = 0.f;
    for (int dc = 0; dc < D; dc += 64) {
        for (int i = threadIdx.x; i < 64 * 32; i += 1024) {
            uk[i] = U[((size_t)k * D + dc) * S + i];
            ul[i] = U[((size_t)l * D + dc) * S + i];
        }
        __syncthreads();
#pragma unroll 8
        for (int d = 0; d < 64; d++)
            c += uk[d * 32 + s] * ul[d * 32 + t];
        __syncthreads();
    }
    if (k == l && s == t) c -= 1.0f;
    float v = c * c;
    __shared__ float red[1024];
    red[threadIdx.x] = v;
    __syncthreads();
    for (int off = 512; off > 0; off >>= 1) {
        if (threadIdx.x < off) red[threadIdx.x] += red[threadIdx.x + off];
        __syncthreads();
    }
    if (threadIdx.x == 0) g_orth[p] = red[0];
}

// ---------------- final scalar assembly ----------------
__global__ void k_final(float* __restrict__ out, int out_size) {
    __shared__ float red[1024];
    int tid = threadIdx.x;
    float v = g_partials[tid] + g_partials[tid + 1024] +
              g_partials[tid + 2048] + g_partials[tid + 3072];
    red[tid] = v;
    __syncthreads();
    for (int off = 512; off > 0; off >>= 1) {
        if (tid < off) red[tid] += red[tid + off];
        __syncthreads();
    }
    if (tid == 0) {
        float orth = 0.f;
        for (int p = 0; p < 10; p++) orth += g_orth[p];
        int base = N * D;
        if (base < out_size) out[base] = orth;
        if (base + 1 < out_size) out[base + 1] = red[0];
        for (int i = 0; i < K; i++)
            if (base + 2 + i < out_size) out[base + 2 + i] = g_w[i];
    }
}

// ---------------- launch ----------------
extern "C" void kernel_launch(void* const* d_in, const int* in_sizes, int n_in,
                              void* d_out, int out_size) {
    const float* hops      = (const float*)d_in[0];
    const float* adj       = (const float*)d_in[1];
    const float* U         = (const float*)d_in[3];
    const float* hw        = (const float*)d_in[4];
    const float* threshold = (const float*)d_in[5];
    const float* lam       = (const float*)d_in[6];
    float* out = (float*)d_out;

    k_w<<<1, 32>>>(hw);
    k_prepW<<<(K * D * S + 255) / 256, 256>>>(U, hw);
    k_csr<<<N / 8, 256>>>(adj);
    {
        dim3 g(N / 64, K);
        k_Z<<<g, 256>>>(hops, U);
    }
    {
        dim3 g(64, K);
        k_gramP<<<g, 1024>>>();
    }
    k_inv<<<K, 1024>>>();
    {
        dim3 b(32, 8), g(N / 8, K);
        k_MZ<<<g, b>>>();
    }
    k_attn<<<(K * N) / 8, 256>>>();
    k_lapO<<<N / 8, 256>>>(lam);
    {
        dim3 g(N / 32, D / 32);
        k_HoutG<<<g, 256>>>(hops, threshold, out);
    }
    k_lap<<<N / 4, 256>>>(out);
    k_orth<<<10, 1024>>>(U);
    k_final<<<1, 1024>>>(out, out_size);
}

// round 4
// speedup vs baseline: 3.2449x; 1.0860x over previous
#include <cuda_runtime.h>
#include <math.h>

#define K 4
#define N 4096
#define D 256
#define S 32
#define MAXDEG 512
#define ETA 0.5f
#define COEFF 0.03125f   // S/(N*EPS^2)

// ---------------- scratch ----------------
__device__ float g_Zt[K * N * S];        // [k][n][s]
__device__ float g_MZt[K * N * S];       // [k][n][s]
__device__ float g_Minv[K * S * S];
__device__ float g_O[(size_t)N * (K * S)];   // O_cat: [n][k*S+s]
__device__ float g_O2[(size_t)N * (K * S)];  // (I - lam*L) @ O_cat
__device__ float g_Wc[K * S * D];        // w_k * U[k]^T : [k*S+s][d]
__device__ float g_gramP[K * 64 * S * S];
__device__ int   g_col[(size_t)N * MAXDEG];
__device__ int   g_deg[N];
__device__ float g_partials[N];
__device__ float g_orth[10];
__device__ int   g_ctr;

__device__ __forceinline__ float warpSum(float v) {
    v += __shfl_xor_sync(0xffffffffu, v, 16);
    v += __shfl_xor_sync(0xffffffffu, v, 8);
    v += __shfl_xor_sync(0xffffffffu, v, 4);
    v += __shfl_xor_sync(0xffffffffu, v, 2);
    v += __shfl_xor_sync(0xffffffffu, v, 1);
    return v;
}

// ---------------- Wc[k*S+s][d] = w_k * U[k][d][s]; also reset counter ----------------
__global__ void k_prepW(const float* __restrict__ U, const float* __restrict__ hw) {
    int idx = blockIdx.x * blockDim.x + threadIdx.x;
    if (idx == 0) g_ctr = 0;
    if (idx >= K * D * S) return;
    int k = idx / (D * S);
    int rem = idx % (D * S);
    int d = rem / S;
    int s = rem % S;
    float m = fmaxf(fmaxf(hw[0], hw[1]), fmaxf(hw[2], hw[3]));
    float e0 = expf(hw[0] - m), e1 = expf(hw[1] - m), e2 = expf(hw[2] - m), e3 = expf(hw[3] - m);
    float sum = e0 + e1 + e2 + e3;
    float wk = (k == 0 ? e0 : k == 1 ? e1 : k == 2 ? e2 : e3) / sum;
    g_Wc[(k * S + s) * D + d] = wk * U[idx];
}

// ---------------- CSR build (warp per row, unrolled x4) ----------------
__global__ void k_csr(const float* __restrict__ A) {
    int n = blockIdx.x * 8 + (threadIdx.x >> 5);
    int lane = threadIdx.x & 31;
    const float* row = A + (size_t)n * N;
    int* dst = g_col + (size_t)n * MAXDEG;
    int cnt = 0;
    for (int base = 0; base < N; base += 128) {
        float a0 = row[base + lane];
        float a1 = row[base + 32 + lane];
        float a2 = row[base + 64 + lane];
        float a3 = row[base + 96 + lane];
        unsigned m0 = __ballot_sync(0xffffffffu, a0 != 0.0f);
        unsigned m1 = __ballot_sync(0xffffffffu, a1 != 0.0f);
        unsigned m2 = __ballot_sync(0xffffffffu, a2 != 0.0f);
        unsigned m3 = __ballot_sync(0xffffffffu, a3 != 0.0f);
        unsigned lm = (1u << lane) - 1u;
        if (a0 != 0.0f) dst[cnt + __popc(m0 & lm)] = base + lane;
        cnt += __popc(m0);
        if (a1 != 0.0f) dst[cnt + __popc(m1 & lm)] = base + 32 + lane;
        cnt += __popc(m1);
        if (a2 != 0.0f) dst[cnt + __popc(m2 & lm)] = base + 64 + lane;
        cnt += __popc(m2);
        if (a3 != 0.0f) dst[cnt + __popc(m3 & lm)] = base + 96 + lane;
        cnt += __popc(m3);
    }
    if (lane == 0) g_deg[n] = min(cnt, MAXDEG);
}

// ---------------- Z = hops[k] @ U[k] : 64n x 32s tile, double-buffered ----------------
__global__ void k_Z(const float* __restrict__ hops, const float* __restrict__ U) {
    __shared__ float hsT[2][32 * 66];  // [dd][r]
    __shared__ float us[2][32 * 36];   // [dd][s]
    int k = blockIdx.y;
    int n0 = blockIdx.x * 64;
    int tx = threadIdx.x;
    int ny = tx >> 3;               // 0..31 (n pair for compute)
    int sx = (tx & 7) * 4;          // s quad for compute
    int rowq = tx >> 3;             // 0..31 (h load row)
    int q = tx & 7;                 // float4 col
    const float* Hb = hops + ((size_t)k * N + n0) * D;
    const float* Ub = U + (size_t)k * D * S;

    float4 h0, h1, u0;
    // prologue: load chunk 0
    h0 = *(const float4*)&Hb[(size_t)rowq * D + q * 4];
    h1 = *(const float4*)&Hb[(size_t)(rowq + 32) * D + q * 4];
    u0 = *(const float4*)&Ub[(size_t)rowq * S + q * 4];
    {
        float* hb = hsT[0];
        hb[(q * 4 + 0) * 66 + rowq] = h0.x;
        hb[(q * 4 + 1) * 66 + rowq] = h0.y;
        hb[(q * 4 + 2) * 66 + rowq] = h0.z;
        hb[(q * 4 + 3) * 66 + rowq] = h0.w;
        hb[(q * 4 + 0) * 66 + rowq + 32] = h1.x;
        hb[(q * 4 + 1) * 66 + rowq + 32] = h1.y;
        hb[(q * 4 + 2) * 66 + rowq + 32] = h1.z;
        hb[(q * 4 + 3) * 66 + rowq + 32] = h1.w;
        *(float4*)&us[0][rowq * 36 + q * 4] = u0;
    }
    __syncthreads();

    float a0x = 0.f, a0y = 0.f, a0z = 0.f, a0w = 0.f;
    float a1x = 0.f, a1y = 0.f, a1z = 0.f, a1w = 0.f;

    for (int ch = 0; ch < 8; ch++) {
        int cur = ch & 1;
        if (ch < 7) {
            int dc = (ch + 1) * 32;
            h0 = *(const float4*)&Hb[(size_t)rowq * D + dc + q * 4];
            h1 = *(const float4*)&Hb[(size_t)(rowq + 32) * D + dc + q * 4];
            u0 = *(const float4*)&Ub[(size_t)(dc + rowq) * S + q * 4];
        }
        const float* hb = hsT[cur];
        const float* ub = us[cur];
#pragma unroll
        for (int d = 0; d < 32; d++) {
            float2 h = *(const float2*)&hb[d * 66 + ny * 2];
            float4 u = *(const float4*)&ub[d * 36 + sx];
            a0x += h.x * u.x; a0y += h.x * u.y; a0z += h.x * u.z; a0w += h.x * u.w;
            a1x += h.y * u.x; a1y += h.y * u.y; a1z += h.y * u.z; a1w += h.y * u.w;
        }
        if (ch < 7) {
            float* hb2 = hsT[cur ^ 1];
            hb2[(q * 4 + 0) * 66 + rowq] = h0.x;
            hb2[(q * 4 + 1) * 66 + rowq] = h0.y;
            hb2[(q * 4 + 2) * 66 + rowq] = h0.z;
            hb2[(q * 4 + 3) * 66 + rowq] = h0.w;
            hb2[(q * 4 + 0) * 66 + rowq + 32] = h1.x;
            hb2[(q * 4 + 1) * 66 + rowq + 32] = h1.y;
            hb2[(q * 4 + 2) * 66 + rowq + 32] = h1.z;
            hb2[(q * 4 + 3) * 66 + rowq + 32] = h1.w;
            *(float4*)&us[cur ^ 1][rowq * 36 + q * 4] = u0;
        }
        __syncthreads();
    }
    size_t base = ((size_t)k * N + n0 + ny * 2) * S + sx;
    *(float4*)&g_Zt[base] = make_float4(a0x, a0y, a0z, a0w);
    *(float4*)&g_Zt[base + S] = make_float4(a1x, a1y, a1z, a1w);
}

// ---------------- merged: partial Grams (blocks 0..255) + orth pairs (256..265) ----------------
__global__ void k_gram_orth(const float* __restrict__ U) {
    __shared__ float sm[5120];
    if (blockIdx.x < 256) {
        int k = blockIdx.x >> 6, chunk = blockIdx.x & 63;
        float* zs = sm;
        const float* Z = g_Zt + ((size_t)k * N + chunk * 64) * S;
        for (int i = threadIdx.x; i < 64 * 32; i += 1024) zs[i] = Z[i];
        __syncthreads();
        int s = threadIdx.x >> 5, t = threadIdx.x & 31;
        float g = 0.f;
#pragma unroll 8
        for (int n = 0; n < 64; n++) g += zs[n * 32 + s] * zs[n * 32 + t];
        g_gramP[(((size_t)k * 64 + chunk) * S + s) * S + t] = g;
    } else {
        const int kk[10] = {0, 0, 0, 0, 1, 1, 1, 2, 2, 3};
        const int ll[10] = {0, 1, 2, 3, 1, 2, 3, 2, 3, 3};
        int p = blockIdx.x - 256;
        int k = kk[p], l = ll[p];
        int s = threadIdx.x >> 5, t = threadIdx.x & 31;
        float* uk = sm;
        float* ul = sm + 2048;
        float* red = sm + 4096;
        float c = 0.f;
        for (int dc = 0; dc < D; dc += 64) {
            for (int i = threadIdx.x; i < 64 * 32; i += 1024) {
                uk[i] = U[((size_t)k * D + dc) * S + i];
                ul[i] = U[((size_t)l * D + dc) * S + i];
            }
            __syncthreads();
#pragma unroll 8
            for (int d = 0; d < 64; d++)
                c += uk[d * 32 + s] * ul[d * 32 + t];
            __syncthreads();
        }
        if (k == l && s == t) c -= 1.0f;
        red[threadIdx.x] = c * c;
        __syncthreads();
        for (int off = 512; off > 0; off >>= 1) {
            if (threadIdx.x < off) red[threadIdx.x] += red[threadIdx.x + off];
            __syncthreads();
        }
        if (threadIdx.x == 0) g_orth[p] = red[0];
    }
}

// ---------------- reduce partial Grams + (I + coeff*G)^-1 Gauss-Jordan ----------------
__global__ void k_inv(void) {
    int k = blockIdx.x;
    int s = threadIdx.x >> 5, t = threadIdx.x & 31;
    float g = 0.f;
    for (int c = 0; c < 64; c++)
        g += g_gramP[(((size_t)k * 64 + c) * S + s) * S + t];

    __shared__ float aug[32][66];
    aug[s][t] = (s == t ? 1.0f : 0.0f) + COEFF * g;
    aug[s][32 + t] = (s == t ? 1.0f : 0.0f);
    __syncthreads();

    int r0 = threadIdx.x >> 6, c0 = threadIdx.x & 63;
    int tid2 = threadIdx.x + 1024;
    int r1 = tid2 >> 6, c1 = tid2 & 63;
    for (int p = 0; p < 32; p++) {
        float inv = 1.0f / aug[p][p];
        float f0 = aug[r0][p], pr0 = aug[p][c0];
        float f1 = aug[r1][p], pr1 = aug[p][c1];
        __syncthreads();
        if (r0 == p) aug[p][c0] = pr0 * inv;
        else         aug[r0][c0] -= f0 * inv * pr0;
        if (r1 == p) aug[p][c1] = pr1 * inv;
        else         aug[r1][c1] -= f1 * inv * pr1;
        __syncthreads();
    }
    g_Minv[k * S * S + s * S + t] = aug[s][32 + t];
}

// ---------------- MZt[k][n][s] = Minv[k] @ Zt rows ----------------
__global__ void k_MZ(void) {
    __shared__ float Minv_sh[32 * 32];
    __shared__ float zsh[8][32];
    int tid = threadIdx.y * 32 + threadIdx.x;
    int k = blockIdx.y;
    for (int i = tid; i < 1024; i += 256) Minv_sh[i] = g_Minv[k * 1024 + i];
    int n = blockIdx.x * 8 + threadIdx.y;
    zsh[threadIdx.y][threadIdx.x] = g_Zt[((size_t)k * N + n) * S + threadIdx.x];
    __syncthreads();
    int s = threadIdx.x;
    float acc = 0.f;
#pragma unroll
    for (int t = 0; t < 32; t++) acc += Minv_sh[s * 32 + t] * zsh[threadIdx.y][t];
    g_MZt[((size_t)k * N + n) * S + s] = acc;
}

// ---------------- sparse attention: warp per (n,k), smem-tiled 32-neighbor chunks ----------------
// Scores are ~[-1,1] (M ~ 129*I), so plain exp (no max subtraction) is exact in fp32.
__global__ void k_attn(void) {
    __shared__ float vsh[8][32 * 33];
    __shared__ float psh[8][32];
    __shared__ float qsh[8][32];
    int w = threadIdx.x >> 5;
    int lane = threadIdx.x & 31;
    int gwarp = blockIdx.x * 8 + w;
    int k = gwarp >> 12;
    int n = gwarp & (N - 1);
    const float* MZ = g_MZt + (size_t)k * N * S;
    const int* cols = g_col + (size_t)n * MAXDEG;
    int dn = g_deg[n];
    qsh[w][lane] = g_Zt[((size_t)k * N + n) * S + lane];
    float* v = vsh[w];
    const float* qv = qsh[w];
    float l = 0.f, acc = 0.f;
    int f = lane & 7;       // float4 index within a v row
    int rr = lane >> 3;     // 0..3: row offset within load pass
    for (int c0 = 0; c0 < dn; c0 += 32) {
        int cs = dn - c0; if (cs > 32) cs = 32;
        int j = (lane < cs) ? cols[c0 + lane] : n;
        __syncwarp();
#pragma unroll
        for (int pss = 0; pss < 8; pss++) {
            int r = pss * 4 + rr;
            int jr = __shfl_sync(0xffffffffu, j, r);
            float4 vv = *(const float4*)&MZ[(size_t)jr * S + f * 4];
            float* dst = &v[r * 33 + f * 4];
            dst[0] = vv.x; dst[1] = vv.y; dst[2] = vv.z; dst[3] = vv.w;
        }
        __syncwarp();
        // phase A: lane j scores its neighbor
        float s0 = 0.f, s1 = 0.f, s2 = 0.f, s3 = 0.f;
        const float* vr = &v[lane * 33];
#pragma unroll
        for (int s = 0; s < 32; s += 4) {
            s0 += qv[s] * vr[s];
            s1 += qv[s + 1] * vr[s + 1];
            s2 += qv[s + 2] * vr[s + 2];
            s3 += qv[s + 3] * vr[s + 3];
        }
        float sc = (s0 + s1) + (s2 + s3);
        float p = (lane < cs) ? __expf(sc) : 0.f;
        l += warpSum(p);
        psh[w][lane] = p;
        __syncwarp();
        // phase B: lane s accumulates weighted sum
        float b0 = 0.f, b1 = 0.f, b2 = 0.f, b3 = 0.f;
        const float* pv = psh[w];
#pragma unroll
        for (int jj = 0; jj < 32; jj += 4) {
            b0 += pv[jj] * v[jj * 33 + lane];
            b1 += pv[jj + 1] * v[(jj + 1) * 33 + lane];
            b2 += pv[jj + 2] * v[(jj + 2) * 33 + lane];
            b3 += pv[jj + 3] * v[(jj + 3) * 33 + lane];
        }
        acc += (b0 + b1) + (b2 + b3);
        __syncwarp();
    }
    g_O[(size_t)n * (K * S) + k * S + lane] = acc / l;
}

// ---------------- O2 = (I - lam*L) @ O_cat ----------------
__global__ void k_lapO(const float* __restrict__ lambda_lap) {
    int n = blockIdx.x * 8 + (threadIdx.x >> 5);
    int lane = threadIdx.x & 31;
    const float4* O = (const float4*)g_O;
    const int* cols = g_col + (size_t)n * MAXDEG;
    int dn = g_deg[n];
    float4 o = O[(size_t)n * 32 + lane];
    float4 s = make_float4(0.f, 0.f, 0.f, 0.f);
    int c = 0;
    for (; c + 2 <= dn; c += 2) {
        float4 v0 = O[(size_t)cols[c] * 32 + lane];
        float4 v1 = O[(size_t)cols[c + 1] * 32 + lane];
        s.x += v0.x + v1.x; s.y += v0.y + v1.y;
        s.z += v0.z + v1.z; s.w += v0.w + v1.w;
    }
    if (c < dn) {
        float4 v = O[(size_t)cols[c] * 32 + lane];
        s.x += v.x; s.y += v.y; s.z += v.z; s.w += v.w;
    }
    float lam = lambda_lap[0];
    float fd = (float)dn;
    float4 r;
    r.x = o.x - lam * (fd * o.x - s.x);
    r.y = o.y - lam * (fd * o.y - s.y);
    r.z = o.z - lam * (fd * o.z - s.z);
    r.w = o.w - lam * (fd * o.w - s.w);
    ((float4*)g_O2)[(size_t)n * 32 + lane] = r;
}

// ---------------- H_out = softthresh(hops0 + ETA * O2 @ Wc) ----------------
__global__ void k_HoutG(const float* __restrict__ hops,
                        const float* __restrict__ threshold,
                        float* __restrict__ out) {
    __shared__ float as[32][33];
    __shared__ float ws[32][33];
    int n0 = blockIdx.x * 32, d0 = blockIdx.y * 32;
    int lane = threadIdx.x & 31;
    int row = threadIdx.x >> 5;
    float acc[4] = {0.f, 0.f, 0.f, 0.f};
    for (int cc = 0; cc < K * S; cc += 32) {
#pragma unroll
        for (int i = 0; i < 4; i++) {
            int r = row + i * 8;
            as[r][lane] = g_O2[(size_t)(n0 + r) * (K * S) + cc + lane];
            ws[r][lane] = g_Wc[(size_t)(cc + r) * D + d0 + lane];
        }
        __syncthreads();
#pragma unroll
        for (int dd = 0; dd < 32; dd++) {
            float wv = ws[dd][lane];
#pragma unroll
            for (int i = 0; i < 4; i++) acc[i] += as[row * 4 + i][dd] * wv;
        }
        __syncthreads();
    }
    float th = threshold[d0 + lane];
#pragma unroll
    for (int i = 0; i < 4; i++) {
        int n = n0 + row * 4 + i;
        float hh = hops[(size_t)n * D + d0 + lane] + ETA * acc[i];
        float ab = fabsf(hh) - th;
        out[(size_t)n * D + d0 + lane] = (ab > 0.f) ? copysignf(ab, hh) : 0.f;
    }
}

// ---------------- lap_smooth partials (symmetric half) + fused final reduce ----------------
__global__ void k_lapF(const float* __restrict__ Hout, const float* __restrict__ hw,
                       float* __restrict__ out, int out_size) {
    int n = blockIdx.x * 4 + (threadIdx.x >> 6);
    int t = threadIdx.x & 63;
    const float4* H = (const float4*)Hout;
    const int* cols = g_col + (size_t)n * MAXDEG;
    int dn = g_deg[n];
    float4 h = H[(size_t)n * 64 + t];
    float4 vs = make_float4(0.f, 0.f, 0.f, 0.f);
    for (int c = 0; c < dn; c++) {
        int j = cols[c];
        if (j >= n) break;
        float4 v = H[(size_t)j * 64 + t];
        vs.x += v.x; vs.y += v.y; vs.z += v.z; vs.w += v.w;
    }
    float fd = (float)dn - 1.0f;
    float dot = fd * (h.x * h.x + h.y * h.y + h.z * h.z + h.w * h.w)
              - 2.0f * (h.x * vs.x + h.y * vs.y + h.z * vs.z + h.w * vs.w);
    dot = warpSum(dot);
    __shared__ float sred[8];
    if ((threadIdx.x & 31) == 0) sred[threadIdx.x >> 5] = dot;
    __syncthreads();
    if (threadIdx.x < 4)
        g_partials[blockIdx.x * 4 + threadIdx.x] =
            sred[threadIdx.x * 2] + sred[threadIdx.x * 2 + 1];

    // last-block fused final reduction
    __threadfence();
    __shared__ int isLast;
    if (threadIdx.x == 0)
        isLast = (atomicAdd(&g_ctr, 1) == (int)gridDim.x - 1) ? 1 : 0;
    __syncthreads();
    if (!isLast) return;
    __threadfence();

    float v = 0.f;
    for (int i = threadIdx.x; i < N; i += 256) v += g_partials[i];
    __shared__ float red2[256];
    red2[threadIdx.x] = v;
    __syncthreads();
    for (int off = 128; off > 0; off >>= 1) {
        if (threadIdx.x < off) red2[threadIdx.x] += red2[threadIdx.x + off];
        __syncthreads();
    }
    if (threadIdx.x == 0) {
        float orth = 0.f;
        for (int p = 0; p < 10; p++) orth += g_orth[p];
        float m = fmaxf(fmaxf(hw[0], hw[1]), fmaxf(hw[2], hw[3]));
        float e0 = expf(hw[0] - m), e1 = expf(hw[1] - m);
        float e2 = expf(hw[2] - m), e3 = expf(hw[3] - m);
        float s = e0 + e1 + e2 + e3;
        int base = N * D;
        if (base < out_size) out[base] = orth;
        if (base + 1 < out_size) out[base + 1] = red2[0];
        if (base + 2 < out_size) out[base + 2] = e0 / s;
        if (base + 3 < out_size) out[base + 3] = e1 / s;
        if (base + 4 < out_size) out[base + 4] = e2 / s;
        if (base + 5 < out_size) out[base + 5] = e3 / s;
    }
}

// ---------------- launch ----------------
extern "C" void kernel_launch(void* const* d_in, const int* in_sizes, int n_in,
                              void* d_out, int out_size) {
    const float* hops      = (const float*)d_in[0];
    const float* adj       = (const float*)d_in[1];
    const float* U         = (const float*)d_in[3];
    const float* hw        = (const float*)d_in[4];
    const float* threshold = (const float*)d_in[5];
    const float* lam       = (const float*)d_in[6];
    float* out = (float*)d_out;

    k_prepW<<<(K * D * S + 255) / 256, 256>>>(U, hw);
    k_csr<<<N / 8, 256>>>(adj);
    {
        dim3 g(N / 64, K);
        k_Z<<<g, 256>>>(hops, U);
    }
    k_gram_orth<<<266, 1024>>>(U);
    k_inv<<<K, 1024>>>();
    {
        dim3 b(32, 8), g(N / 8, K);
        k_MZ<<<g, b>>>();
    }
    k_attn<<<(K * N) / 8, 256>>>();
    k_lapO<<<N / 8, 256>>>(lam);
    {
        dim3 g(N / 32, D / 32);
        k_HoutG<<<g, 256>>>(hops, threshold, out);
    }
    k_lapF<<<N / 4, 256>>>(out, hw, out, out_size);
}

// round 5
// speedup vs baseline: 3.4991x; 1.0783x over previous
#include <cuda_runtime.h>
#include <math.h>

#define K 4
#define N 4096
#define D 256
#define S 32
#define MAXDEG 512
#define ETA 0.5f
#define COEFF 0.03125f   // S/(N*EPS^2)

// ---------------- scratch ----------------
__device__ float g_Zt[K * N * S];        // [k][n][s]
__device__ float g_MZt[K * N * S];       // [k][n][s]
__device__ float g_Minv[K * S * S];
__device__ float g_O[(size_t)N * (K * S)];   // O_cat: [n][k*S+s]
__device__ float g_O2[(size_t)N * (K * S)];  // (I - lam*L) @ O_cat
__device__ float g_Wc[K * S * D];        // w_k * U[k]^T : [k*S+s][d]
__device__ float g_gramP[K * 32 * S * S];
__device__ int   g_col[(size_t)N * MAXDEG];
__device__ int   g_deg[N];
__device__ float g_partials[N];
__device__ float g_orth[10];
__device__ int   g_ctr;       // zero-init; self-resetting
__device__ int   g_ctrK[K];   // zero-init; self-resetting

__device__ __forceinline__ float warpSum(float v) {
    v += __shfl_xor_sync(0xffffffffu, v, 16);
    v += __shfl_xor_sync(0xffffffffu, v, 8);
    v += __shfl_xor_sync(0xffffffffu, v, 4);
    v += __shfl_xor_sync(0xffffffffu, v, 2);
    v += __shfl_xor_sync(0xffffffffu, v, 1);
    return v;
}

// ---------------- CSR build (warp per row, float4 + 4 ballots per 128 cols) ----------------
__global__ void k_csr(const float* __restrict__ A) {
    int n = blockIdx.x * 8 + (threadIdx.x >> 5);
    int lane = threadIdx.x & 31;
    const float4* row = (const float4*)(A + (size_t)n * N);
    int* dst = g_col + (size_t)n * MAXDEG;
    unsigned lm = (1u << lane) - 1u;
    int cnt = 0;
    for (int base = 0; base < N / 4; base += 32) {
        float4 a = row[base + lane];
        unsigned m0 = __ballot_sync(0xffffffffu, a.x != 0.0f);
        unsigned m1 = __ballot_sync(0xffffffffu, a.y != 0.0f);
        unsigned m2 = __ballot_sync(0xffffffffu, a.z != 0.0f);
        unsigned m3 = __ballot_sync(0xffffffffu, a.w != 0.0f);
        int pre = cnt + __popc(m0 & lm) + __popc(m1 & lm)
                      + __popc(m2 & lm) + __popc(m3 & lm);
        int j0 = (base + lane) * 4;
        if (a.x != 0.0f) dst[pre] = j0;
        int o1 = pre + ((m0 >> lane) & 1);
        if (a.y != 0.0f) dst[o1] = j0 + 1;
        int o2 = o1 + ((m1 >> lane) & 1);
        if (a.z != 0.0f) dst[o2] = j0 + 2;
        int o3 = o2 + ((m2 >> lane) & 1);
        if (a.w != 0.0f) dst[o3] = j0 + 3;
        cnt += __popc(m0) + __popc(m1) + __popc(m2) + __popc(m3);
    }
    if (lane == 0) g_deg[n] = min(cnt, MAXDEG);
}

// ---------------- Z = hops[k] @ U[k] : 64n x 32s tile, double-buffered ----------------
__global__ void k_Z(const float* __restrict__ hops, const float* __restrict__ U) {
    __shared__ float hsT[2][32 * 66];  // [dd][r]
    __shared__ float us[2][32 * 36];   // [dd][s]
    int k = blockIdx.y;
    int n0 = blockIdx.x * 64;
    int tx = threadIdx.x;
    int ny = tx >> 3;
    int sx = (tx & 7) * 4;
    int rowq = tx >> 3;
    int q = tx & 7;
    const float* Hb = hops + ((size_t)k * N + n0) * D;
    const float* Ub = U + (size_t)k * D * S;

    float4 h0, h1, u0;
    h0 = *(const float4*)&Hb[(size_t)rowq * D + q * 4];
    h1 = *(const float4*)&Hb[(size_t)(rowq + 32) * D + q * 4];
    u0 = *(const float4*)&Ub[(size_t)rowq * S + q * 4];
    {
        float* hb = hsT[0];
        hb[(q * 4 + 0) * 66 + rowq] = h0.x;
        hb[(q * 4 + 1) * 66 + rowq] = h0.y;
        hb[(q * 4 + 2) * 66 + rowq] = h0.z;
        hb[(q * 4 + 3) * 66 + rowq] = h0.w;
        hb[(q * 4 + 0) * 66 + rowq + 32] = h1.x;
        hb[(q * 4 + 1) * 66 + rowq + 32] = h1.y;
        hb[(q * 4 + 2) * 66 + rowq + 32] = h1.z;
        hb[(q * 4 + 3) * 66 + rowq + 32] = h1.w;
        *(float4*)&us[0][rowq * 36 + q * 4] = u0;
    }
    __syncthreads();

    float a0x = 0.f, a0y = 0.f, a0z = 0.f, a0w = 0.f;
    float a1x = 0.f, a1y = 0.f, a1z = 0.f, a1w = 0.f;

    for (int ch = 0; ch < 8; ch++) {
        int cur = ch & 1;
        if (ch < 7) {
            int dc = (ch + 1) * 32;
            h0 = *(const float4*)&Hb[(size_t)rowq * D + dc + q * 4];
            h1 = *(const float4*)&Hb[(size_t)(rowq + 32) * D + dc + q * 4];
            u0 = *(const float4*)&Ub[(size_t)(dc + rowq) * S + q * 4];
        }
        const float* hb = hsT[cur];
        const float* ub = us[cur];
#pragma unroll
        for (int d = 0; d < 32; d++) {
            float2 h = *(const float2*)&hb[d * 66 + ny * 2];
            float4 u = *(const float4*)&ub[d * 36 + sx];
            a0x += h.x * u.x; a0y += h.x * u.y; a0z += h.x * u.z; a0w += h.x * u.w;
            a1x += h.y * u.x; a1y += h.y * u.y; a1z += h.y * u.z; a1w += h.y * u.w;
        }
        if (ch < 7) {
            float* hb2 = hsT[cur ^ 1];
            hb2[(q * 4 + 0) * 66 + rowq] = h0.x;
            hb2[(q * 4 + 1) * 66 + rowq] = h0.y;
            hb2[(q * 4 + 2) * 66 + rowq] = h0.z;
            hb2[(q * 4 + 3) * 66 + rowq] = h0.w;
            hb2[(q * 4 + 0) * 66 + rowq + 32] = h1.x;
            hb2[(q * 4 + 1) * 66 + rowq + 32] = h1.y;
            hb2[(q * 4 + 2) * 66 + rowq + 32] = h1.z;
            hb2[(q * 4 + 3) * 66 + rowq + 32] = h1.w;
            *(float4*)&us[cur ^ 1][rowq * 36 + q * 4] = u0;
        }
        __syncthreads();
    }
    size_t base = ((size_t)k * N + n0 + ny * 2) * S + sx;
    *(float4*)&g_Zt[base] = make_float4(a0x, a0y, a0z, a0w);
    *(float4*)&g_Zt[base + S] = make_float4(a1x, a1y, a1z, a1w);
}

// ---------------- mega kernel A ----------------
// blocks 0..127   : Gram partials (chunk=128 rows); last block per k sums + inverts (GJ)
// blocks 128..137 : orth pairs
// blocks 138..145 : Wc prep
__global__ void __launch_bounds__(1024) k_megaA(const float* __restrict__ U,
                                                const float* __restrict__ hw) {
    __shared__ float sm[5120];
    int tid = threadIdx.x;
    if (blockIdx.x < 128) {
        int k = blockIdx.x >> 5;        // 0..3
        int chunk = blockIdx.x & 31;    // 0..31
        float* zs = sm;                 // 128 x 32 = 4096 floats
        const float4* Z4 = (const float4*)(g_Zt + ((size_t)k * N + chunk * 128) * S);
        ((float4*)zs)[tid] = Z4[tid];
        __syncthreads();
        int s = tid >> 5, t = tid & 31;
        float g0 = 0.f, g1 = 0.f, g2 = 0.f, g3 = 0.f;
#pragma unroll 8
        for (int n = 0; n < 128; n += 4) {
            g0 += zs[(n + 0) * 32 + s] * zs[(n + 0) * 32 + t];
            g1 += zs[(n + 1) * 32 + s] * zs[(n + 1) * 32 + t];
            g2 += zs[(n + 2) * 32 + s] * zs[(n + 2) * 32 + t];
            g3 += zs[(n + 3) * 32 + s] * zs[(n + 3) * 32 + t];
        }
        g_gramP[(((size_t)k * 32 + chunk) * S + s) * S + t] = (g0 + g1) + (g2 + g3);
        __threadfence();
        __shared__ int isLast;
        if (tid == 0) {
            int v = atomicAdd(&g_ctrK[k], 1);
            isLast = (v == 31);
            if (v == 31) atomicExch(&g_ctrK[k], 0);   // self-reset for graph replay
        }
        __syncthreads();
        if (!isLast) return;
        __threadfence();
        // sum partials + Gauss-Jordan inversion of I + coeff*G
        float g = 0.f;
        for (int c = 0; c < 32; c++)
            g += g_gramP[(((size_t)k * 32 + c) * S + s) * S + t];
        float (*aug)[66] = (float(*)[66])sm;   // reuse (zs dead)
        __syncthreads();
        aug[s][t] = (s == t ? 1.0f : 0.0f) + COEFF * g;
        aug[s][32 + t] = (s == t ? 1.0f : 0.0f);
        __syncthreads();
        int r0 = tid >> 6, c0 = tid & 63;
        int tid2 = tid + 1024;
        int r1 = tid2 >> 6, c1 = tid2 & 63;
        for (int p = 0; p < 32; p++) {
            float inv = 1.0f / aug[p][p];
            float f0 = aug[r0][p], pr0 = aug[p][c0];
            float f1 = aug[r1][p], pr1 = aug[p][c1];
            __syncthreads();
            if (r0 == p) aug[p][c0] = pr0 * inv;
            else         aug[r0][c0] -= f0 * inv * pr0;
            if (r1 == p) aug[p][c1] = pr1 * inv;
            else         aug[r1][c1] -= f1 * inv * pr1;
            __syncthreads();
        }
        g_Minv[k * S * S + s * S + t] = aug[s][32 + t];
    } else if (blockIdx.x < 138) {
        const int kk[10] = {0, 0, 0, 0, 1, 1, 1, 2, 2, 3};
        const int ll[10] = {0, 1, 2, 3, 1, 2, 3, 2, 3, 3};
        int p = blockIdx.x - 128;
        int k = kk[p], l = ll[p];
        int s = tid >> 5, t = tid & 31;
        float* uk = sm;
        float* ul = sm + 2048;
        float* red = sm + 4096;
        float c = 0.f;
        for (int dc = 0; dc < D; dc += 64) {
            for (int i = tid; i < 64 * 32; i += 1024) {
                uk[i] = U[((size_t)k * D + dc) * S + i];
                ul[i] = U[((size_t)l * D + dc) * S + i];
            }
            __syncthreads();
#pragma unroll 8
            for (int d = 0; d < 64; d++)
                c += uk[d * 32 + s] * ul[d * 32 + t];
            __syncthreads();
        }
        if (k == l && s == t) c -= 1.0f;
        red[tid] = c * c;
        __syncthreads();
        for (int off = 512; off > 0; off >>= 1) {
            if (tid < off) red[tid] += red[tid + off];
            __syncthreads();
        }
        if (tid == 0) g_orth[p] = red[0];
    } else {
        // Wc prep: 8 blocks x 1024 threads x 4 elems = K*D*S
        float m = fmaxf(fmaxf(hw[0], hw[1]), fmaxf(hw[2], hw[3]));
        float e0 = expf(hw[0] - m), e1 = expf(hw[1] - m);
        float e2 = expf(hw[2] - m), e3 = expf(hw[3] - m);
        float sum = e0 + e1 + e2 + e3;
        int base = ((blockIdx.x - 138) * 1024 + tid) * 4;
        float4 u4 = *(const float4*)&U[base];
        int k = base / (D * S);
        int rem = base % (D * S);
        int d = rem / S;
        int s = rem % S;
        float wk = (k == 0 ? e0 : k == 1 ? e1 : k == 2 ? e2 : e3) / sum;
        g_Wc[(k * S + s + 0) * D + d] = wk * u4.x;
        g_Wc[(k * S + s + 1) * D + d] = wk * u4.y;
        g_Wc[(k * S + s + 2) * D + d] = wk * u4.z;
        g_Wc[(k * S + s + 3) * D + d] = wk * u4.w;
    }
}

// ---------------- MZt[k][n][s] = Minv[k] @ Zt rows ----------------
__global__ void k_MZ(void) {
    __shared__ float Minv_sh[32 * 32];
    __shared__ float zsh[8][32];
    int tid = threadIdx.y * 32 + threadIdx.x;
    int k = blockIdx.y;
    for (int i = tid; i < 1024; i += 256) Minv_sh[i] = g_Minv[k * 1024 + i];
    int n = blockIdx.x * 8 + threadIdx.y;
    zsh[threadIdx.y][threadIdx.x] = g_Zt[((size_t)k * N + n) * S + threadIdx.x];
    __syncthreads();
    int s = threadIdx.x;
    float acc = 0.f;
#pragma unroll
    for (int t = 0; t < 32; t++) acc += Minv_sh[s * 32 + t] * zsh[threadIdx.y][t];
    g_MZt[((size_t)k * N + n) * S + s] = acc;
}

// ---------------- sparse attention: warp per (n,k), smem-tiled 32-neighbor chunks ----------------
__global__ void k_attn(void) {
    __shared__ float vsh[8][32 * 33];
    __shared__ float psh[8][32];
    __shared__ float qsh[8][32];
    int w = threadIdx.x >> 5;
    int lane = threadIdx.x & 31;
    int gwarp = blockIdx.x * 8 + w;
    int k = gwarp >> 12;
    int n = gwarp & (N - 1);
    const float* MZ = g_MZt + (size_t)k * N * S;
    const int* cols = g_col + (size_t)n * MAXDEG;
    int dn = g_deg[n];
    qsh[w][lane] = g_Zt[((size_t)k * N + n) * S + lane];
    float* v = vsh[w];
    const float* qv = qsh[w];
    float l = 0.f, acc = 0.f;
    int f = lane & 7;
    int rr = lane >> 3;
    for (int c0 = 0; c0 < dn; c0 += 32) {
        int cs = dn - c0; if (cs > 32) cs = 32;
        int j = (lane < cs) ? cols[c0 + lane] : n;
        __syncwarp();
#pragma unroll
        for (int pss = 0; pss < 8; pss++) {
            int r = pss * 4 + rr;
            int jr = __shfl_sync(0xffffffffu, j, r);
            float4 vv = *(const float4*)&MZ[(size_t)jr * S + f * 4];
            float* dst = &v[r * 33 + f * 4];
            dst[0] = vv.x; dst[1] = vv.y; dst[2] = vv.z; dst[3] = vv.w;
        }
        __syncwarp();
        float s0 = 0.f, s1 = 0.f, s2 = 0.f, s3 = 0.f;
        const float* vr = &v[lane * 33];
#pragma unroll
        for (int s = 0; s < 32; s += 4) {
            s0 += qv[s] * vr[s];
            s1 += qv[s + 1] * vr[s + 1];
            s2 += qv[s + 2] * vr[s + 2];
            s3 += qv[s + 3] * vr[s + 3];
        }
        float sc = (s0 + s1) + (s2 + s3);
        float p = (lane < cs) ? __expf(sc) : 0.f;
        l += warpSum(p);
        psh[w][lane] = p;
        __syncwarp();
        float b0 = 0.f, b1 = 0.f, b2 = 0.f, b3 = 0.f;
        const float* pv = psh[w];
#pragma unroll
        for (int jj = 0; jj < 32; jj += 4) {
            b0 += pv[jj] * v[jj * 33 + lane];
            b1 += pv[jj + 1] * v[(jj + 1) * 33 + lane];
            b2 += pv[jj + 2] * v[(jj + 2) * 33 + lane];
            b3 += pv[jj + 3] * v[(jj + 3) * 33 + lane];
        }
        acc += (b0 + b1) + (b2 + b3);
        __syncwarp();
    }
    g_O[(size_t)n * (K * S) + k * S + lane] = acc / l;
}

// ---------------- O2 = (I - lam*L) @ O_cat ----------------
__global__ void k_lapO(const float* __restrict__ lambda_lap) {
    int n = blockIdx.x * 8 + (threadIdx.x >> 5);
    int lane = threadIdx.x & 31;
    const float4* O = (const float4*)g_O;
    const int* cols = g_col + (size_t)n * MAXDEG;
    int dn = g_deg[n];
    float4 o = O[(size_t)n * 32 + lane];
    float4 s = make_float4(0.f, 0.f, 0.f, 0.f);
    int c = 0;
    for (; c + 2 <= dn; c += 2) {
        float4 v0 = O[(size_t)cols[c] * 32 + lane];
        float4 v1 = O[(size_t)cols[c + 1] * 32 + lane];
        s.x += v0.x + v1.x; s.y += v0.y + v1.y;
        s.z += v0.z + v1.z; s.w += v0.w + v1.w;
    }
    if (c < dn) {
        float4 v = O[(size_t)cols[c] * 32 + lane];
        s.x += v.x; s.y += v.y; s.z += v.z; s.w += v.w;
    }
    float lam = lambda_lap[0];
    float fd = (float)dn;
    float4 r;
    r.x = o.x - lam * (fd * o.x - s.x);
    r.y = o.y - lam * (fd * o.y - s.y);
    r.z = o.z - lam * (fd * o.z - s.z);
    r.w = o.w - lam * (fd * o.w - s.w);
    ((float4*)g_O2)[(size_t)n * 32 + lane] = r;
}

// ---------------- H_out = softthresh(hops0 + ETA * O2 @ Wc) ----------------
__global__ void k_HoutG(const float* __restrict__ hops,
                        const float* __restrict__ threshold,
                        float* __restrict__ out) {
    __shared__ float as[32][33];
    __shared__ float ws[32][33];
    int n0 = blockIdx.x * 32, d0 = blockIdx.y * 32;
    int lane = threadIdx.x & 31;
    int row = threadIdx.x >> 5;
    float acc[4] = {0.f, 0.f, 0.f, 0.f};
    for (int cc = 0; cc < K * S; cc += 32) {
#pragma unroll
        for (int i = 0; i < 4; i++) {
            int r = row + i * 8;
            as[r][lane] = g_O2[(size_t)(n0 + r) * (K * S) + cc + lane];
            ws[r][lane] = g_Wc[(size_t)(cc + r) * D + d0 + lane];
        }
        __syncthreads();
#pragma unroll
        for (int dd = 0; dd < 32; dd++) {
            float wv = ws[dd][lane];
#pragma unroll
            for (int i = 0; i < 4; i++) acc[i] += as[row * 4 + i][dd] * wv;
        }
        __syncthreads();
    }
    float th = threshold[d0 + lane];
#pragma unroll
    for (int i = 0; i < 4; i++) {
        int n = n0 + row * 4 + i;
        float hh = hops[(size_t)n * D + d0 + lane] + ETA * acc[i];
        float ab = fabsf(hh) - th;
        out[(size_t)n * D + d0 + lane] = (ab > 0.f) ? copysignf(ab, hh) : 0.f;
    }
}

// ---------------- lap_smooth partials (symmetric half) + fused final reduce ----------------
__global__ void k_lapF(const float* __restrict__ Hout, const float* __restrict__ hw,
                       float* __restrict__ out, int out_size) {
    int n = blockIdx.x * 4 + (threadIdx.x >> 6);
    int t = threadIdx.x & 63;
    const float4* H = (const float4*)Hout;
    const int* cols = g_col + (size_t)n * MAXDEG;
    int dn = g_deg[n];
    float4 h = H[(size_t)n * 64 + t];
    float4 vs = make_float4(0.f, 0.f, 0.f, 0.f);
    for (int c = 0; c < dn; c++) {
        int j = cols[c];
        if (j >= n) break;
        float4 v = H[(size_t)j * 64 + t];
        vs.x += v.x; vs.y += v.y; vs.z += v.z; vs.w += v.w;
    }
    float fd = (float)dn - 1.0f;
    float dot = fd * (h.x * h.x + h.y * h.y + h.z * h.z + h.w * h.w)
              - 2.0f * (h.x * vs.x + h.y * vs.y + h.z * vs.z + h.w * vs.w);
    dot = warpSum(dot);
    __shared__ float sred[8];
    if ((threadIdx.x & 31) == 0) sred[threadIdx.x >> 5] = dot;
    __syncthreads();
    if (threadIdx.x < 4)
        g_partials[blockIdx.x * 4 + threadIdx.x] =
            sred[threadIdx.x * 2] + sred[threadIdx.x * 2 + 1];

    __threadfence();
    __shared__ int isLast;
    if (threadIdx.x == 0) {
        int v = atomicAdd(&g_ctr, 1);
        isLast = (v == (int)gridDim.x - 1) ? 1 : 0;
        if (isLast) atomicExch(&g_ctr, 0);   // self-reset for graph replay
    }
    __syncthreads();
    if (!isLast) return;
    __threadfence();

    float v = 0.f;
    for (int i = threadIdx.x; i < N; i += 256) v += g_partials[i];
    __shared__ float red2[256];
    red2[threadIdx.x] = v;
    __syncthreads();
    for (int off = 128; off > 0; off >>= 1) {
        if (threadIdx.x < off) red2[threadIdx.x] += red2[threadIdx.x + off];
        __syncthreads();
    }
    if (threadIdx.x == 0) {
        float orth = 0.f;
        for (int p = 0; p < 10; p++) orth += g_orth[p];
        float m = fmaxf(fmaxf(hw[0], hw[1]), fmaxf(hw[2], hw[3]));
        float e0 = expf(hw[0] - m), e1 = expf(hw[1] - m);
        float e2 = expf(hw[2] - m), e3 = expf(hw[3] - m);
        float s = e0 + e1 + e2 + e3;
        int base = N * D;
        if (base < out_size) out[base] = orth;
        if (base + 1 < out_size) out[base + 1] = red2[0];
        if (base + 2 < out_size) out[base + 2] = e0 / s;
        if (base + 3 < out_size) out[base + 3] = e1 / s;
        if (base + 4 < out_size) out[base + 4] = e2 / s;
        if (base + 5 < out_size) out[base + 5] = e3 / s;
    }
}

// ---------------- launch ----------------
extern "C" void kernel_launch(void* const* d_in, const int* in_sizes, int n_in,
                              void* d_out, int out_size) {
    const float* hops      = (const float*)d_in[0];
    const float* adj       = (const float*)d_in[1];
    const float* U         = (const float*)d_in[3];
    const float* hw        = (const float*)d_in[4];
    const float* threshold = (const float*)d_in[5];
    const float* lam       = (const float*)d_in[6];
    float* out = (float*)d_out;

    k_csr<<<N / 8, 256>>>(adj);
    {
        dim3 g(N / 64, K);
        k_Z<<<g, 256>>>(hops, U);
    }
    k_megaA<<<146, 1024>>>(U, hw);
    {
        dim3 b(32, 8), g(N / 8, K);
        k_MZ<<<g, b>>>();
    }
    k_attn<<<(K * N) / 8, 256>>>();
    k_lapO<<<N / 8, 256>>>(lam);
    {
        dim3 g(N / 32, D / 32);
        k_HoutG<<<g, 256>>>(hops, threshold, out);
    }
    k_lapF<<<N / 4, 256>>>(out, hw, out, out_size);
}

// round 6
// speedup vs baseline: 3.8500x; 1.1003x over previous
#include <cuda_runtime.h>
#include <math.h>

#define K 4
#define N 4096
#define D 256
#define S 32
#define MAXDEG 512
#define ETA 0.5f
#define COEFF 0.03125f   // S/(N*EPS^2)

// ---------------- scratch ----------------
__device__ float g_Zt[K * N * S];        // [k][n][s]
__device__ float g_MZt[K * N * S];       // [k][n][s]
__device__ float g_Minv[K * S * S];
__device__ float g_O[(size_t)N * (K * S)];   // O_cat: [n][k*S+s]
__device__ float g_O2[(size_t)N * (K * S)];  // (I - lam*L) @ O_cat
__device__ float g_Wc[K * S * D];        // w_k * U[k]^T : [k*S+s][d]
__device__ float g_gramP[K * 32 * S * S];
__device__ int   g_col[(size_t)N * MAXDEG];
__device__ int   g_deg[N];
__device__ float g_partials[N];
__device__ float g_orth[10];
__device__ int   g_ctr;       // zero-init; self-resetting
__device__ int   g_ctrK[K];   // zero-init; self-resetting

__device__ __forceinline__ float warpSum(float v) {
    v += __shfl_xor_sync(0xffffffffu, v, 16);
    v += __shfl_xor_sync(0xffffffffu, v, 8);
    v += __shfl_xor_sync(0xffffffffu, v, 4);
    v += __shfl_xor_sync(0xffffffffu, v, 2);
    v += __shfl_xor_sync(0xffffffffu, v, 1);
    return v;
}

// ---------------- CSR build (warp per row, float4 + 4 ballots per 128 cols) ----------------
__global__ void k_csr(const float* __restrict__ A) {
    int n = blockIdx.x * 8 + (threadIdx.x >> 5);
    int lane = threadIdx.x & 31;
    const float4* row = (const float4*)(A + (size_t)n * N);
    int* dst = g_col + (size_t)n * MAXDEG;
    unsigned lm = (1u << lane) - 1u;
    int cnt = 0;
    for (int base = 0; base < N / 4; base += 32) {
        float4 a = row[base + lane];
        unsigned m0 = __ballot_sync(0xffffffffu, a.x != 0.0f);
        unsigned m1 = __ballot_sync(0xffffffffu, a.y != 0.0f);
        unsigned m2 = __ballot_sync(0xffffffffu, a.z != 0.0f);
        unsigned m3 = __ballot_sync(0xffffffffu, a.w != 0.0f);
        int pre = cnt + __popc(m0 & lm) + __popc(m1 & lm)
                      + __popc(m2 & lm) + __popc(m3 & lm);
        int j0 = (base + lane) * 4;
        if (a.x != 0.0f) dst[pre] = j0;
        int o1 = pre + ((m0 >> lane) & 1);
        if (a.y != 0.0f) dst[o1] = j0 + 1;
        int o2 = o1 + ((m1 >> lane) & 1);
        if (a.z != 0.0f) dst[o2] = j0 + 2;
        int o3 = o2 + ((m2 >> lane) & 1);
        if (a.w != 0.0f) dst[o3] = j0 + 3;
        cnt += __popc(m0) + __popc(m1) + __popc(m2) + __popc(m3);
    }
    if (lane == 0) g_deg[n] = min(cnt, MAXDEG);
}

// ---------------- Z = hops[k] @ U[k] : 64n x 32s tile, double-buffered ----------------
__global__ void k_Z(const float* __restrict__ hops, const float* __restrict__ U) {
    __shared__ float hsT[2][32 * 66];  // [dd][r]
    __shared__ float us[2][32 * 36];   // [dd][s]
    int k = blockIdx.y;
    int n0 = blockIdx.x * 64;
    int tx = threadIdx.x;
    int ny = tx >> 3;
    int sx = (tx & 7) * 4;
    int rowq = tx >> 3;
    int q = tx & 7;
    const float* Hb = hops + ((size_t)k * N + n0) * D;
    const float* Ub = U + (size_t)k * D * S;

    float4 h0, h1, u0;
    h0 = *(const float4*)&Hb[(size_t)rowq * D + q * 4];
    h1 = *(const float4*)&Hb[(size_t)(rowq + 32) * D + q * 4];
    u0 = *(const float4*)&Ub[(size_t)rowq * S + q * 4];
    {
        float* hb = hsT[0];
        hb[(q * 4 + 0) * 66 + rowq] = h0.x;
        hb[(q * 4 + 1) * 66 + rowq] = h0.y;
        hb[(q * 4 + 2) * 66 + rowq] = h0.z;
        hb[(q * 4 + 3) * 66 + rowq] = h0.w;
        hb[(q * 4 + 0) * 66 + rowq + 32] = h1.x;
        hb[(q * 4 + 1) * 66 + rowq + 32] = h1.y;
        hb[(q * 4 + 2) * 66 + rowq + 32] = h1.z;
        hb[(q * 4 + 3) * 66 + rowq + 32] = h1.w;
        *(float4*)&us[0][rowq * 36 + q * 4] = u0;
    }
    __syncthreads();

    float a0x = 0.f, a0y = 0.f, a0z = 0.f, a0w = 0.f;
    float a1x = 0.f, a1y = 0.f, a1z = 0.f, a1w = 0.f;

    for (int ch = 0; ch < 8; ch++) {
        int cur = ch & 1;
        if (ch < 7) {
            int dc = (ch + 1) * 32;
            h0 = *(const float4*)&Hb[(size_t)rowq * D + dc + q * 4];
            h1 = *(const float4*)&Hb[(size_t)(rowq + 32) * D + dc + q * 4];
            u0 = *(const float4*)&Ub[(size_t)(dc + rowq) * S + q * 4];
        }
        const float* hb = hsT[cur];
        const float* ub = us[cur];
#pragma unroll
        for (int d = 0; d < 32; d++) {
            float2 h = *(const float2*)&hb[d * 66 + ny * 2];
            float4 u = *(const float4*)&ub[d * 36 + sx];
            a0x += h.x * u.x; a0y += h.x * u.y; a0z += h.x * u.z; a0w += h.x * u.w;
            a1x += h.y * u.x; a1y += h.y * u.y; a1z += h.y * u.z; a1w += h.y * u.w;
        }
        if (ch < 7) {
            float* hb2 = hsT[cur ^ 1];
            hb2[(q * 4 + 0) * 66 + rowq] = h0.x;
            hb2[(q * 4 + 1) * 66 + rowq] = h0.y;
            hb2[(q * 4 + 2) * 66 + rowq] = h0.z;
            hb2[(q * 4 + 3) * 66 + rowq] = h0.w;
            hb2[(q * 4 + 0) * 66 + rowq + 32] = h1.x;
            hb2[(q * 4 + 1) * 66 + rowq + 32] = h1.y;
            hb2[(q * 4 + 2) * 66 + rowq + 32] = h1.z;
            hb2[(q * 4 + 3) * 66 + rowq + 32] = h1.w;
            *(float4*)&us[cur ^ 1][rowq * 36 + q * 4] = u0;
        }
        __syncthreads();
    }
    size_t base = ((size_t)k * N + n0 + ny * 2) * S + sx;
    *(float4*)&g_Zt[base] = make_float4(a0x, a0y, a0z, a0w);
    *(float4*)&g_Zt[base + S] = make_float4(a1x, a1y, a1z, a1w);
}

// ---------------- mega kernel A ----------------
// blocks 0..127   : Gram partials (chunk=128 rows); last block per k sums + inverts (GJ)
// blocks 128..137 : orth pairs
// blocks 138..145 : Wc prep
__global__ void __launch_bounds__(1024) k_megaA(const float* __restrict__ U,
                                                const float* __restrict__ hw) {
    __shared__ float sm[5120];
    int tid = threadIdx.x;
    if (blockIdx.x < 128) {
        int k = blockIdx.x >> 5;
        int chunk = blockIdx.x & 31;
        float* zs = sm;
        const float4* Z4 = (const float4*)(g_Zt + ((size_t)k * N + chunk * 128) * S);
        ((float4*)zs)[tid] = Z4[tid];
        __syncthreads();
        int s = tid >> 5, t = tid & 31;
        float g0 = 0.f, g1 = 0.f, g2 = 0.f, g3 = 0.f;
#pragma unroll 8
        for (int n = 0; n < 128; n += 4) {
            g0 += zs[(n + 0) * 32 + s] * zs[(n + 0) * 32 + t];
            g1 += zs[(n + 1) * 32 + s] * zs[(n + 1) * 32 + t];
            g2 += zs[(n + 2) * 32 + s] * zs[(n + 2) * 32 + t];
            g3 += zs[(n + 3) * 32 + s] * zs[(n + 3) * 32 + t];
        }
        g_gramP[(((size_t)k * 32 + chunk) * S + s) * S + t] = (g0 + g1) + (g2 + g3);
        __threadfence();
        __shared__ int isLast;
        if (tid == 0) {
            int v = atomicAdd(&g_ctrK[k], 1);
            isLast = (v == 31);
            if (v == 31) atomicExch(&g_ctrK[k], 0);
        }
        __syncthreads();
        if (!isLast) return;
        __threadfence();
        float g = 0.f;
        for (int c = 0; c < 32; c++)
            g += g_gramP[(((size_t)k * 32 + c) * S + s) * S + t];
        float (*aug)[66] = (float(*)[66])sm;
        __syncthreads();
        aug[s][t] = (s == t ? 1.0f : 0.0f) + COEFF * g;
        aug[s][32 + t] = (s == t ? 1.0f : 0.0f);
        __syncthreads();
        int r0 = tid >> 6, c0 = tid & 63;
        int tid2 = tid + 1024;
        int r1 = tid2 >> 6, c1 = tid2 & 63;
        for (int p = 0; p < 32; p++) {
            float inv = 1.0f / aug[p][p];
            float f0 = aug[r0][p], pr0 = aug[p][c0];
            float f1 = aug[r1][p], pr1 = aug[p][c1];
            __syncthreads();
            if (r0 == p) aug[p][c0] = pr0 * inv;
            else         aug[r0][c0] -= f0 * inv * pr0;
            if (r1 == p) aug[p][c1] = pr1 * inv;
            else         aug[r1][c1] -= f1 * inv * pr1;
            __syncthreads();
        }
        g_Minv[k * S * S + s * S + t] = aug[s][32 + t];
    } else if (blockIdx.x < 138) {
        const int kk[10] = {0, 0, 0, 0, 1, 1, 1, 2, 2, 3};
        const int ll[10] = {0, 1, 2, 3, 1, 2, 3, 2, 3, 3};
        int p = blockIdx.x - 128;
        int k = kk[p], l = ll[p];
        int s = tid >> 5, t = tid & 31;
        float* uk = sm;
        float* ul = sm + 2048;
        float* red = sm + 4096;
        float c = 0.f;
        for (int dc = 0; dc < D; dc += 64) {
            for (int i = tid; i < 64 * 32; i += 1024) {
                uk[i] = U[((size_t)k * D + dc) * S + i];
                ul[i] = U[((size_t)l * D + dc) * S + i];
            }
            __syncthreads();
#pragma unroll 8
            for (int d = 0; d < 64; d++)
                c += uk[d * 32 + s] * ul[d * 32 + t];
            __syncthreads();
        }
        if (k == l && s == t) c -= 1.0f;
        red[tid] = c * c;
        __syncthreads();
        for (int off = 512; off > 0; off >>= 1) {
            if (tid < off) red[tid] += red[tid + off];
            __syncthreads();
        }
        if (tid == 0) g_orth[p] = red[0];
    } else {
        float m = fmaxf(fmaxf(hw[0], hw[1]), fmaxf(hw[2], hw[3]));
        float e0 = expf(hw[0] - m), e1 = expf(hw[1] - m);
        float e2 = expf(hw[2] - m), e3 = expf(hw[3] - m);
        float sum = e0 + e1 + e2 + e3;
        int base = ((blockIdx.x - 138) * 1024 + tid) * 4;
        float4 u4 = *(const float4*)&U[base];
        int k = base / (D * S);
        int rem = base % (D * S);
        int d = rem / S;
        int s = rem % S;
        float wk = (k == 0 ? e0 : k == 1 ? e1 : k == 2 ? e2 : e3) / sum;
        g_Wc[(k * S + s + 0) * D + d] = wk * u4.x;
        g_Wc[(k * S + s + 1) * D + d] = wk * u4.y;
        g_Wc[(k * S + s + 2) * D + d] = wk * u4.z;
        g_Wc[(k * S + s + 3) * D + d] = wk * u4.w;
    }
}

// ---------------- MZt = Minv[k] @ Zt rows : conflict-free, 4 rows/warp ----------------
// block = 256 threads (8 warps); each block does 32 n-rows of one k.
__global__ void k_MZ(void) {
    __shared__ float Msh[32 * 33];     // padded: lane reads s*?? -> conflict-free
    __shared__ float zsh[32 * 33];     // [row][t] padded
    int k = blockIdx.y;
    int n0 = blockIdx.x * 32;
    int tid = threadIdx.x;
    int w = tid >> 5;                  // warp 0..7
    int lane = tid & 31;               // = output s index

    // stage Minv (transposed is fine: M symmetric? No! M_inv IS symmetric (inverse of SPD).)
    // Msh[t*33 + s] = Minv[s][t]; symmetric -> load linear and index either way.
    {
        // 1024 floats, 256 threads, float4
        float4 v = ((const float4*)(g_Minv + k * S * S))[tid];
        int r = (tid * 4) >> 5;        // row s
        int c = (tid * 4) & 31;        // col t
        float* dst = &Msh[r * 33 + c];
        dst[0] = v.x; dst[1] = v.y; dst[2] = v.z; dst[3] = v.w;
    }
    // stage 32 Z rows: row r = tid>>3, quad q = tid&7
    {
        int r = tid >> 3, q = tid & 7;
        float4 v = *(const float4*)&g_Zt[((size_t)k * N + n0 + r) * S + q * 4];
        float* dst = &zsh[r * 33 + q * 4];
        dst[0] = v.x; dst[1] = v.y; dst[2] = v.z; dst[3] = v.w;
    }
    __syncthreads();

    // each warp computes 4 n-rows; lane = s
    float a0 = 0.f, a1 = 0.f, a2 = 0.f, a3 = 0.f;
    const float* z0 = &zsh[(w * 4 + 0) * 33];
    const float* z1 = &zsh[(w * 4 + 1) * 33];
    const float* z2 = &zsh[(w * 4 + 2) * 33];
    const float* z3 = &zsh[(w * 4 + 3) * 33];
#pragma unroll
    for (int t = 0; t < 32; t++) {
        float mv = Msh[t * 33 + lane];     // M[t][s] = M[s][t] (symmetric); conflict-free
        a0 += mv * z0[t];                  // z reads are warp-broadcast
        a1 += mv * z1[t];
        a2 += mv * z2[t];
        a3 += mv * z3[t];
    }
    size_t base = ((size_t)k * N + n0 + w * 4) * S + lane;
    g_MZt[base] = a0;
    g_MZt[base + S] = a1;
    g_MZt[base + 2 * S] = a2;
    g_MZt[base + 3 * S] = a3;
}

// ---------------- sparse attention: warp per (n,k), smem-tiled 32-neighbor chunks ----------------
__global__ void k_attn(void) {
    __shared__ float vsh[8][32 * 33];
    __shared__ float psh[8][32];
    __shared__ float qsh[8][32];
    int w = threadIdx.x >> 5;
    int lane = threadIdx.x & 31;
    int gwarp = blockIdx.x * 8 + w;
    int k = gwarp >> 12;
    int n = gwarp & (N - 1);
    const float* MZ = g_MZt + (size_t)k * N * S;
    const int* cols = g_col + (size_t)n * MAXDEG;
    int dn = g_deg[n];
    qsh[w][lane] = g_Zt[((size_t)k * N + n) * S + lane];
    float* v = vsh[w];
    const float* qv = qsh[w];
    float l = 0.f, acc = 0.f;
    int f = lane & 7;
    int rr = lane >> 3;
    for (int c0 = 0; c0 < dn; c0 += 32) {
        int cs = dn - c0; if (cs > 32) cs = 32;
        int j = (lane < cs) ? cols[c0 + lane] : n;
        __syncwarp();
#pragma unroll
        for (int pss = 0; pss < 8; pss++) {
            int r = pss * 4 + rr;
            int jr = __shfl_sync(0xffffffffu, j, r);
            float4 vv = *(const float4*)&MZ[(size_t)jr * S + f * 4];
            float* dst = &v[r * 33 + f * 4];
            dst[0] = vv.x; dst[1] = vv.y; dst[2] = vv.z; dst[3] = vv.w;
        }
        __syncwarp();
        float s0 = 0.f, s1 = 0.f, s2 = 0.f, s3 = 0.f;
        const float* vr = &v[lane * 33];
#pragma unroll
        for (int s = 0; s < 32; s += 4) {
            s0 += qv[s] * vr[s];
            s1 += qv[s + 1] * vr[s + 1];
            s2 += qv[s + 2] * vr[s + 2];
            s3 += qv[s + 3] * vr[s + 3];
        }
        float sc = (s0 + s1) + (s2 + s3);
        float p = (lane < cs) ? __expf(sc) : 0.f;
        l += warpSum(p);
        psh[w][lane] = p;
        __syncwarp();
        float b0 = 0.f, b1 = 0.f, b2 = 0.f, b3 = 0.f;
        const float* pv = psh[w];
#pragma unroll
        for (int jj = 0; jj < 32; jj += 4) {
            b0 += pv[jj] * v[jj * 33 + lane];
            b1 += pv[jj + 1] * v[(jj + 1) * 33 + lane];
            b2 += pv[jj + 2] * v[(jj + 2) * 33 + lane];
            b3 += pv[jj + 3] * v[(jj + 3) * 33 + lane];
        }
        acc += (b0 + b1) + (b2 + b3);
        __syncwarp();
    }
    g_O[(size_t)n * (K * S) + k * S + lane] = acc / l;
}

// ---------------- O2 = (I - lam*L) @ O_cat ----------------
__global__ void k_lapO(const float* __restrict__ lambda_lap) {
    int n = blockIdx.x * 8 + (threadIdx.x >> 5);
    int lane = threadIdx.x & 31;
    const float4* O = (const float4*)g_O;
    const int* cols = g_col + (size_t)n * MAXDEG;
    int dn = g_deg[n];
    float4 o = O[(size_t)n * 32 + lane];
    float4 s = make_float4(0.f, 0.f, 0.f, 0.f);
    int c = 0;
    for (; c + 2 <= dn; c += 2) {
        float4 v0 = O[(size_t)cols[c] * 32 + lane];
        float4 v1 = O[(size_t)cols[c + 1] * 32 + lane];
        s.x += v0.x + v1.x; s.y += v0.y + v1.y;
        s.z += v0.z + v1.z; s.w += v0.w + v1.w;
    }
    if (c < dn) {
        float4 v = O[(size_t)cols[c] * 32 + lane];
        s.x += v.x; s.y += v.y; s.z += v.z; s.w += v.w;
    }
    float lam = lambda_lap[0];
    float fd = (float)dn;
    float4 r;
    r.x = o.x - lam * (fd * o.x - s.x);
    r.y = o.y - lam * (fd * o.y - s.y);
    r.z = o.z - lam * (fd * o.z - s.z);
    r.w = o.w - lam * (fd * o.w - s.w);
    ((float4*)g_O2)[(size_t)n * 32 + lane] = r;
}

// ---------------- H_out = softthresh(hops0 + ETA * O2 @ Wc) ----------------
__global__ void k_HoutG(const float* __restrict__ hops,
                        const float* __restrict__ threshold,
                        float* __restrict__ out) {
    __shared__ float as[32][33];
    __shared__ float ws[32][33];
    int n0 = blockIdx.x * 32, d0 = blockIdx.y * 32;
    int lane = threadIdx.x & 31;
    int row = threadIdx.x >> 5;
    float acc[4] = {0.f, 0.f, 0.f, 0.f};
    for (int cc = 0; cc < K * S; cc += 32) {
#pragma unroll
        for (int i = 0; i < 4; i++) {
            int r = row + i * 8;
            as[r][lane] = g_O2[(size_t)(n0 + r) * (K * S) + cc + lane];
            ws[r][lane] = g_Wc[(size_t)(cc + r) * D + d0 + lane];
        }
        __syncthreads();
#pragma unroll
        for (int dd = 0; dd < 32; dd++) {
            float wv = ws[dd][lane];
#pragma unroll
            for (int i = 0; i < 4; i++) acc[i] += as[row * 4 + i][dd] * wv;
        }
        __syncthreads();
    }
    float th = threshold[d0 + lane];
#pragma unroll
    for (int i = 0; i < 4; i++) {
        int n = n0 + row * 4 + i;
        float hh = hops[(size_t)n * D + d0 + lane] + ETA * acc[i];
        float ab = fabsf(hh) - th;
        out[(size_t)n * D + d0 + lane] = (ab > 0.f) ? copysignf(ab, hh) : 0.f;
    }
}

// ---------------- lap_smooth partials (symmetric half) + fused final reduce ----------------
__global__ void k_lapF(const float* __restrict__ Hout, const float* __restrict__ hw,
                       float* __restrict__ out, int out_size) {
    int n = blockIdx.x * 4 + (threadIdx.x >> 6);
    int t = threadIdx.x & 63;
    const float4* H = (const float4*)Hout;
    const int* cols = g_col + (size_t)n * MAXDEG;
    int dn = g_deg[n];
    float4 h = H[(size_t)n * 64 + t];
    float4 vs = make_float4(0.f, 0.f, 0.f, 0.f);
    for (int c = 0; c < dn; c++) {
        int j = cols[c];
        if (j >= n) break;
        float4 v = H[(size_t)j * 64 + t];
        vs.x += v.x; vs.y += v.y; vs.z += v.z; vs.w += v.w;
    }
    float fd = (float)dn - 1.0f;
    float dot = fd * (h.x * h.x + h.y * h.y + h.z * h.z + h.w * h.w)
              - 2.0f * (h.x * vs.x + h.y * vs.y + h.z * vs.z + h.w * vs.w);
    dot = warpSum(dot);
    __shared__ float sred[8];
    if ((threadIdx.x & 31) == 0) sred[threadIdx.x >> 5] = dot;
    __syncthreads();
    if (threadIdx.x < 4)
        g_partials[blockIdx.x * 4 + threadIdx.x] =
            sred[threadIdx.x * 2] + sred[threadIdx.x * 2 + 1];

    __threadfence();
    __shared__ int isLast;
    if (threadIdx.x == 0) {
        int v = atomicAdd(&g_ctr, 1);
        isLast = (v == (int)gridDim.x - 1) ? 1 : 0;
        if (isLast) atomicExch(&g_ctr, 0);
    }
    __syncthreads();
    if (!isLast) return;
    __threadfence();

    float v = 0.f;
    for (int i = threadIdx.x; i < N; i += 256) v += g_partials[i];
    __shared__ float red2[256];
    red2[threadIdx.x] = v;
    __syncthreads();
    for (int off = 128; off > 0; off >>= 1) {
        if (threadIdx.x < off) red2[threadIdx.x] += red2[threadIdx.x + off];
        __syncthreads();
    }
    if (threadIdx.x == 0) {
        float orth = 0.f;
        for (int p = 0; p < 10; p++) orth += g_orth[p];
        float m = fmaxf(fmaxf(hw[0], hw[1]), fmaxf(hw[2], hw[3]));
        float e0 = expf(hw[0] - m), e1 = expf(hw[1] - m);
        float e2 = expf(hw[2] - m), e3 = expf(hw[3] - m);
        float s = e0 + e1 + e2 + e3;
        int base = N * D;
        if (base < out_size) out[base] = orth;
        if (base + 1 < out_size) out[base + 1] = red2[0];
        if (base + 2 < out_size) out[base + 2] = e0 / s;
        if (base + 3 < out_size) out[base + 3] = e1 / s;
        if (base + 4 < out_size) out[base + 4] = e2 / s;
        if (base + 5 < out_size) out[base + 5] = e3 / s;
    }
}

// ---------------- launch ----------------
extern "C" void kernel_launch(void* const* d_in, const int* in_sizes, int n_in,
                              void* d_out, int out_size) {
    const float* hops      = (const float*)d_in[0];
    const float* adj       = (const float*)d_in[1];
    const float* U         = (const float*)d_in[3];
    const float* hw        = (const float*)d_in[4];
    const float* threshold = (const float*)d_in[5];
    const float* lam       = (const float*)d_in[6];
    float* out = (float*)d_out;

    k_csr<<<N / 8, 256>>>(adj);
    {
        dim3 g(N / 64, K);
        k_Z<<<g, 256>>>(hops, U);
    }
    k_megaA<<<146, 1024>>>(U, hw);
    {
        dim3 g(N / 32, K);
        k_MZ<<<g, 256>>>();
    }
    k_attn<<<(K * N) / 8, 256>>>();
    k_lapO<<<N / 8, 256>>>(lam);
    {
        dim3 g(N / 32, D / 32);
        k_HoutG<<<g, 256>>>(hops, threshold, out);
    }
    k_lapF<<<N / 4, 256>>>(out, hw, out, out_size);
}

// round 7
// speedup vs baseline: 4.1445x; 1.0765x over previous
#include <cuda_runtime.h>
#include <math.h>

#define K 4
#define N 4096
#define D 256
#define S 32
#define MAXDEG 512
#define ETA 0.5f
#define COEFF 0.03125f   // S/(N*EPS^2)

// ---------------- scratch ----------------
__device__ float g_Zt[K * N * S];        // [k][n][s]
__device__ float g_MZt[K * N * S];       // [k][n][s]
__device__ float g_Minv[K * S * S];
__device__ float g_O[(size_t)N * (K * S)];   // O_cat: [n][k*S+s]
__device__ float g_O2[(size_t)N * (K * S)];  // (I - lam*L) @ O_cat
__device__ float g_Wc[K * S * D];        // w_k * U[k]^T : [k*S+s][d]
__device__ float g_gramP[K * 32 * S * S];
__device__ int   g_col[(size_t)N * MAXDEG];
__device__ int   g_deg[N];
__device__ float g_partials[N];
__device__ float g_orth[10];
__device__ int   g_ctr;       // zero-init; self-resetting
__device__ int   g_ctrK[K];   // zero-init; self-resetting

__device__ __forceinline__ float warpSum(float v) {
    v += __shfl_xor_sync(0xffffffffu, v, 16);
    v += __shfl_xor_sync(0xffffffffu, v, 8);
    v += __shfl_xor_sync(0xffffffffu, v, 4);
    v += __shfl_xor_sync(0xffffffffu, v, 2);
    v += __shfl_xor_sync(0xffffffffu, v, 1);
    return v;
}

// ================= mega kernel 1: Z (0..255) | CSR (256..767) | Wc (768..799) | orth (800..809) =================
__global__ void __launch_bounds__(256) k_mega1(const float* __restrict__ hops,
                                               const float* __restrict__ adj,
                                               const float* __restrict__ U,
                                               const float* __restrict__ hw) {
    __shared__ float sm[6528];
    int bx = blockIdx.x;
    int tid = threadIdx.x;

    if (bx < 256) {
        // ---------- Z = hops[k] @ U[k] : 64n x 32s tile, double-buffered ----------
        int k = bx >> 6;
        int n0 = (bx & 63) * 64;
        float* hsT0 = sm;            // 32*66
        float* hsT1 = sm + 2112;
        float* us0  = sm + 4224;     // 32*36
        float* us1  = sm + 5376;
        int ny = tid >> 3;
        int sx = (tid & 7) * 4;
        int rowq = tid >> 3;
        int q = tid & 7;
        const float* Hb = hops + ((size_t)k * N + n0) * D;
        const float* Ub = U + (size_t)k * D * S;

        float4 h0, h1, u0;
        h0 = *(const float4*)&Hb[(size_t)rowq * D + q * 4];
        h1 = *(const float4*)&Hb[(size_t)(rowq + 32) * D + q * 4];
        u0 = *(const float4*)&Ub[(size_t)rowq * S + q * 4];
        {
            float* hb = hsT0;
            hb[(q * 4 + 0) * 66 + rowq] = h0.x;
            hb[(q * 4 + 1) * 66 + rowq] = h0.y;
            hb[(q * 4 + 2) * 66 + rowq] = h0.z;
            hb[(q * 4 + 3) * 66 + rowq] = h0.w;
            hb[(q * 4 + 0) * 66 + rowq + 32] = h1.x;
            hb[(q * 4 + 1) * 66 + rowq + 32] = h1.y;
            hb[(q * 4 + 2) * 66 + rowq + 32] = h1.z;
            hb[(q * 4 + 3) * 66 + rowq + 32] = h1.w;
            *(float4*)&us0[rowq * 36 + q * 4] = u0;
        }
        __syncthreads();

        float a0x = 0.f, a0y = 0.f, a0z = 0.f, a0w = 0.f;
        float a1x = 0.f, a1y = 0.f, a1z = 0.f, a1w = 0.f;

        for (int ch = 0; ch < 8; ch++) {
            const float* hb = (ch & 1) ? hsT1 : hsT0;
            const float* ub = (ch & 1) ? us1 : us0;
            if (ch < 7) {
                int dc = (ch + 1) * 32;
                h0 = *(const float4*)&Hb[(size_t)rowq * D + dc + q * 4];
                h1 = *(const float4*)&Hb[(size_t)(rowq + 32) * D + dc + q * 4];
                u0 = *(const float4*)&Ub[(size_t)(dc + rowq) * S + q * 4];
            }
#pragma unroll
            for (int d = 0; d < 32; d++) {
                float2 h = *(const float2*)&hb[d * 66 + ny * 2];
                float4 u = *(const float4*)&ub[d * 36 + sx];
                a0x += h.x * u.x; a0y += h.x * u.y; a0z += h.x * u.z; a0w += h.x * u.w;
                a1x += h.y * u.x; a1y += h.y * u.y; a1z += h.y * u.z; a1w += h.y * u.w;
            }
            if (ch < 7) {
                float* hb2 = (ch & 1) ? hsT0 : hsT1;
                float* ub2 = (ch & 1) ? us0 : us1;
                hb2[(q * 4 + 0) * 66 + rowq] = h0.x;
                hb2[(q * 4 + 1) * 66 + rowq] = h0.y;
                hb2[(q * 4 + 2) * 66 + rowq] = h0.z;
                hb2[(q * 4 + 3) * 66 + rowq] = h0.w;
                hb2[(q * 4 + 0) * 66 + rowq + 32] = h1.x;
                hb2[(q * 4 + 1) * 66 + rowq + 32] = h1.y;
                hb2[(q * 4 + 2) * 66 + rowq + 32] = h1.z;
                hb2[(q * 4 + 3) * 66 + rowq + 32] = h1.w;
                *(float4*)&ub2[rowq * 36 + q * 4] = u0;
            }
            __syncthreads();
        }
        size_t base = ((size_t)k * N + n0 + ny * 2) * S + sx;
        *(float4*)&g_Zt[base] = make_float4(a0x, a0y, a0z, a0w);
        *(float4*)&g_Zt[base + S] = make_float4(a1x, a1y, a1z, a1w);
    } else if (bx < 768) {
        // ---------- CSR build (warp per row, float4 + 4 ballots per 128 cols) ----------
        int n = (bx - 256) * 8 + (tid >> 5);
        int lane = tid & 31;
        const float4* row = (const float4*)(adj + (size_t)n * N);
        int* dst = g_col + (size_t)n * MAXDEG;
        unsigned lm = (1u << lane) - 1u;
        int cnt = 0;
        for (int base = 0; base < N / 4; base += 32) {
            float4 a = row[base + lane];
            unsigned m0 = __ballot_sync(0xffffffffu, a.x != 0.0f);
            unsigned m1 = __ballot_sync(0xffffffffu, a.y != 0.0f);
            unsigned m2 = __ballot_sync(0xffffffffu, a.z != 0.0f);
            unsigned m3 = __ballot_sync(0xffffffffu, a.w != 0.0f);
            int pre = cnt + __popc(m0 & lm) + __popc(m1 & lm)
                          + __popc(m2 & lm) + __popc(m3 & lm);
            int j0 = (base + lane) * 4;
            if (a.x != 0.0f) dst[pre] = j0;
            int o1 = pre + ((m0 >> lane) & 1);
            if (a.y != 0.0f) dst[o1] = j0 + 1;
            int o2 = o1 + ((m1 >> lane) & 1);
            if (a.z != 0.0f) dst[o2] = j0 + 2;
            int o3 = o2 + ((m2 >> lane) & 1);
            if (a.w != 0.0f) dst[o3] = j0 + 3;
            cnt += __popc(m0) + __popc(m1) + __popc(m2) + __popc(m3);
        }
        if (lane == 0) g_deg[n] = min(cnt, MAXDEG);
    } else if (bx < 800) {
        // ---------- Wc[k*S+s][d] = w_k * U[k][d][s] ----------
        float m = fmaxf(fmaxf(hw[0], hw[1]), fmaxf(hw[2], hw[3]));
        float e0 = expf(hw[0] - m), e1 = expf(hw[1] - m);
        float e2 = expf(hw[2] - m), e3 = expf(hw[3] - m);
        float sum = e0 + e1 + e2 + e3;
        int base = ((bx - 768) * 256 + tid) * 4;
        float4 u4 = *(const float4*)&U[base];
        int k = base / (D * S);
        int rem = base % (D * S);
        int d = rem / S;
        int s = rem % S;
        float wk = (k == 0 ? e0 : k == 1 ? e1 : k == 2 ? e2 : e3) / sum;
        g_Wc[(k * S + s + 0) * D + d] = wk * u4.x;
        g_Wc[(k * S + s + 1) * D + d] = wk * u4.y;
        g_Wc[(k * S + s + 2) * D + d] = wk * u4.z;
        g_Wc[(k * S + s + 3) * D + d] = wk * u4.w;
    } else {
        // ---------- orth pair (s,t) dots; 4 t per thread ----------
        const int kk[10] = {0, 0, 0, 0, 1, 1, 1, 2, 2, 3};
        const int ll[10] = {0, 1, 2, 3, 1, 2, 3, 2, 3, 3};
        int p = bx - 800;
        int k = kk[p], l = ll[p];
        int s = tid >> 3;
        int t0 = (tid & 7) * 4;
        float* uk = sm;
        float* ul = sm + 2048;
        float* red = sm + 4096;
        float c0 = 0.f, c1 = 0.f, c2 = 0.f, c3 = 0.f;
        for (int dc = 0; dc < D; dc += 64) {
            for (int i = tid; i < 2048; i += 256) {
                uk[i] = U[((size_t)k * D + dc) * S + i];
                ul[i] = U[((size_t)l * D + dc) * S + i];
            }
            __syncthreads();
#pragma unroll 8
            for (int d = 0; d < 64; d++) {
                float a = uk[d * 32 + s];
                float4 b = *(const float4*)&ul[d * 32 + t0];
                c0 += a * b.x; c1 += a * b.y; c2 += a * b.z; c3 += a * b.w;
            }
            __syncthreads();
        }
        if (k == l) {
            if (s == t0 + 0) c0 -= 1.0f;
            if (s == t0 + 1) c1 -= 1.0f;
            if (s == t0 + 2) c2 -= 1.0f;
            if (s == t0 + 3) c3 -= 1.0f;
        }
        red[tid] = (c0 * c0 + c1 * c1) + (c2 * c2 + c3 * c3);
        __syncthreads();
        for (int off = 128; off > 0; off >>= 1) {
            if (tid < off) red[tid] += red[tid + off];
            __syncthreads();
        }
        if (tid == 0) g_orth[p] = red[0];
    }
}

// ================= gram partials + last-block-per-k inversion =================
__global__ void __launch_bounds__(1024) k_gram(void) {
    __shared__ float sm[4224];
    int tid = threadIdx.x;
    int k = blockIdx.x >> 5;
    int chunk = blockIdx.x & 31;
    float* zs = sm;
    const float4* Z4 = (const float4*)(g_Zt + ((size_t)k * N + chunk * 128) * S);
    ((float4*)zs)[tid] = Z4[tid];
    __syncthreads();
    int s = tid >> 5, t = tid & 31;
    float g0 = 0.f, g1 = 0.f, g2 = 0.f, g3 = 0.f;
#pragma unroll 8
    for (int n = 0; n < 128; n += 4) {
        g0 += zs[(n + 0) * 32 + s] * zs[(n + 0) * 32 + t];
        g1 += zs[(n + 1) * 32 + s] * zs[(n + 1) * 32 + t];
        g2 += zs[(n + 2) * 32 + s] * zs[(n + 2) * 32 + t];
        g3 += zs[(n + 3) * 32 + s] * zs[(n + 3) * 32 + t];
    }
    g_gramP[(((size_t)k * 32 + chunk) * S + s) * S + t] = (g0 + g1) + (g2 + g3);
    __threadfence();
    __shared__ int isLast;
    if (tid == 0) {
        int v = atomicAdd(&g_ctrK[k], 1);
        isLast = (v == 31);
        if (v == 31) atomicExch(&g_ctrK[k], 0);
    }
    __syncthreads();
    if (!isLast) return;
    __threadfence();
    float g = 0.f;
    for (int c = 0; c < 32; c++)
        g += g_gramP[(((size_t)k * 32 + c) * S + s) * S + t];
    float (*aug)[66] = (float(*)[66])sm;
    __syncthreads();
    aug[s][t] = (s == t ? 1.0f : 0.0f) + COEFF * g;
    aug[s][32 + t] = (s == t ? 1.0f : 0.0f);
    __syncthreads();
    int r0 = tid >> 6, c0 = tid & 63;
    int tid2 = tid + 1024;
    int r1 = tid2 >> 6, c1 = tid2 & 63;
    for (int p = 0; p < 32; p++) {
        float inv = 1.0f / aug[p][p];
        float f0 = aug[r0][p], pr0 = aug[p][c0];
        float f1 = aug[r1][p], pr1 = aug[p][c1];
        __syncthreads();
        if (r0 == p) aug[p][c0] = pr0 * inv;
        else         aug[r0][c0] -= f0 * inv * pr0;
        if (r1 == p) aug[p][c1] = pr1 * inv;
        else         aug[r1][c1] -= f1 * inv * pr1;
        __syncthreads();
    }
    g_Minv[k * S * S + s * S + t] = aug[s][32 + t];
}

// ================= MZt = Minv[k] @ Zt rows : conflict-free, 4 rows/warp =================
__global__ void k_MZ(void) {
    __shared__ float Msh[32 * 33];
    __shared__ float zsh[32 * 33];
    int k = blockIdx.y;
    int n0 = blockIdx.x * 32;
    int tid = threadIdx.x;
    int w = tid >> 5;
    int lane = tid & 31;
    {
        float4 v = ((const float4*)(g_Minv + k * S * S))[tid];
        int r = (tid * 4) >> 5;
        int c = (tid * 4) & 31;
        float* dst = &Msh[r * 33 + c];
        dst[0] = v.x; dst[1] = v.y; dst[2] = v.z; dst[3] = v.w;
    }
    {
        int r = tid >> 3, q = tid & 7;
        float4 v = *(const float4*)&g_Zt[((size_t)k * N + n0 + r) * S + q * 4];
        float* dst = &zsh[r * 33 + q * 4];
        dst[0] = v.x; dst[1] = v.y; dst[2] = v.z; dst[3] = v.w;
    }
    __syncthreads();
    float a0 = 0.f, a1 = 0.f, a2 = 0.f, a3 = 0.f;
    const float* z0 = &zsh[(w * 4 + 0) * 33];
    const float* z1 = &zsh[(w * 4 + 1) * 33];
    const float* z2 = &zsh[(w * 4 + 2) * 33];
    const float* z3 = &zsh[(w * 4 + 3) * 33];
#pragma unroll
    for (int t = 0; t < 32; t++) {
        float mv = Msh[t * 33 + lane];
        a0 += mv * z0[t];
        a1 += mv * z1[t];
        a2 += mv * z2[t];
        a3 += mv * z3[t];
    }
    size_t base = ((size_t)k * N + n0 + w * 4) * S + lane;
    g_MZt[base] = a0;
    g_MZt[base + S] = a1;
    g_MZt[base + 2 * S] = a2;
    g_MZt[base + 3 * S] = a3;
}

// ================= sparse attention: warp per (n,k), float4 smem phases =================
__global__ void k_attn(void) {
    __shared__ float vsh[8][32 * 36];   // stride 36: float4-aligned, conflict-free
    __shared__ float psh[8][32];
    __shared__ float qsh[8][32];
    int w = threadIdx.x >> 5;
    int lane = threadIdx.x & 31;
    int gwarp = blockIdx.x * 8 + w;
    int k = gwarp >> 12;
    int n = gwarp & (N - 1);
    const float* MZ = g_MZt + (size_t)k * N * S;
    const int* cols = g_col + (size_t)n * MAXDEG;
    int dn = g_deg[n];
    qsh[w][lane] = g_Zt[((size_t)k * N + n) * S + lane];
    float* v = vsh[w];
    float l = 0.f, acc = 0.f;
    int f = lane & 7;
    int rr = lane >> 3;
    const float4* qv4 = (const float4*)qsh[w];
    const float4* pv4 = (const float4*)psh[w];
    for (int c0 = 0; c0 < dn; c0 += 32) {
        int cs = dn - c0; if (cs > 32) cs = 32;
        int j = (lane < cs) ? cols[c0 + lane] : n;
        __syncwarp();
#pragma unroll
        for (int pss = 0; pss < 8; pss++) {
            int r = pss * 4 + rr;
            int jr = __shfl_sync(0xffffffffu, j, r);
            float4 vv = *(const float4*)&MZ[(size_t)jr * S + f * 4];
            *(float4*)&v[r * 36 + f * 4] = vv;
        }
        __syncwarp();
        // phase A: lane scores its neighbor (row read, float4)
        float s0 = 0.f, s1 = 0.f, s2 = 0.f, s3 = 0.f;
        const float4* vr4 = (const float4*)&v[lane * 36];
#pragma unroll
        for (int i = 0; i < 8; i++) {
            float4 a = qv4[i];
            float4 b = vr4[i];
            s0 += a.x * b.x; s1 += a.y * b.y; s2 += a.z * b.z; s3 += a.w * b.w;
        }
        float sc = (s0 + s1) + (s2 + s3);
        float p = (lane < cs) ? __expf(sc) : 0.f;
        l += warpSum(p);
        psh[w][lane] = p;
        __syncwarp();
        // phase B: lane = s accumulates weighted column
        float b0 = 0.f, b1 = 0.f, b2 = 0.f, b3 = 0.f;
#pragma unroll
        for (int i = 0; i < 8; i++) {
            float4 p4 = pv4[i];
            int jj = i * 4;
            b0 += p4.x * v[jj * 36 + lane];
            b1 += p4.y * v[(jj + 1) * 36 + lane];
            b2 += p4.z * v[(jj + 2) * 36 + lane];
            b3 += p4.w * v[(jj + 3) * 36 + lane];
        }
        acc += (b0 + b1) + (b2 + b3);
        __syncwarp();
    }
    g_O[(size_t)n * (K * S) + k * S + lane] = acc / l;
}

// ================= O2 = (I - lam*L) @ O_cat =================
__global__ void k_lapO(const float* __restrict__ lambda_lap) {
    int n = blockIdx.x * 8 + (threadIdx.x >> 5);
    int lane = threadIdx.x & 31;
    const float4* O = (const float4*)g_O;
    const int* cols = g_col + (size_t)n * MAXDEG;
    int dn = g_deg[n];
    float4 o = O[(size_t)n * 32 + lane];
    float4 s = make_float4(0.f, 0.f, 0.f, 0.f);
    int c = 0;
    for (; c + 2 <= dn; c += 2) {
        float4 v0 = O[(size_t)cols[c] * 32 + lane];
        float4 v1 = O[(size_t)cols[c + 1] * 32 + lane];
        s.x += v0.x + v1.x; s.y += v0.y + v1.y;
        s.z += v0.z + v1.z; s.w += v0.w + v1.w;
    }
    if (c < dn) {
        float4 v = O[(size_t)cols[c] * 32 + lane];
        s.x += v.x; s.y += v.y; s.z += v.z; s.w += v.w;
    }
    float lam = lambda_lap[0];
    float fd = (float)dn;
    float4 r;
    r.x = o.x - lam * (fd * o.x - s.x);
    r.y = o.y - lam * (fd * o.y - s.y);
    r.z = o.z - lam * (fd * o.z - s.z);
    r.w = o.w - lam * (fd * o.w - s.w);
    ((float4*)g_O2)[(size_t)n * 32 + lane] = r;
}

// ================= H_out = softthresh(hops0 + ETA * O2 @ Wc) =================
__global__ void k_HoutG(const float* __restrict__ hops,
                        const float* __restrict__ threshold,
                        float* __restrict__ out) {
    __shared__ float as[32][33];
    __shared__ float ws[32][33];
    int n0 = blockIdx.x * 32, d0 = blockIdx.y * 32;
    int lane = threadIdx.x & 31;
    int row = threadIdx.x >> 5;
    float acc[4] = {0.f, 0.f, 0.f, 0.f};
    for (int cc = 0; cc < K * S; cc += 32) {
#pragma unroll
        for (int i = 0; i < 4; i++) {
            int r = row + i * 8;
            as[r][lane] = g_O2[(size_t)(n0 + r) * (K * S) + cc + lane];
            ws[r][lane] = g_Wc[(size_t)(cc + r) * D + d0 + lane];
        }
        __syncthreads();
#pragma unroll
        for (int dd = 0; dd < 32; dd++) {
            float wv = ws[dd][lane];
#pragma unroll
            for (int i = 0; i < 4; i++) acc[i] += as[row * 4 + i][dd] * wv;
        }
        __syncthreads();
    }
    float th = threshold[d0 + lane];
#pragma unroll
    for (int i = 0; i < 4; i++) {
        int n = n0 + row * 4 + i;
        float hh = hops[(size_t)n * D + d0 + lane] + ETA * acc[i];
        float ab = fabsf(hh) - th;
        out[(size_t)n * D + d0 + lane] = (ab > 0.f) ? copysignf(ab, hh) : 0.f;
    }
}

// ================= lap_smooth partials (symmetric half) + fused final =================
__global__ void k_lapF(const float* __restrict__ Hout, const float* __restrict__ hw,
                       float* __restrict__ out, int out_size) {
    __shared__ int hd[4];
    if (threadIdx.x < 4) {
        int nn = blockIdx.x * 4 + threadIdx.x;
        const int* cc = g_col + (size_t)nn * MAXDEG;
        int lo = 0, hi = g_deg[nn];
        while (lo < hi) {
            int mid = (lo + hi) >> 1;
            if (cc[mid] < nn) lo = mid + 1; else hi = mid;
        }
        hd[threadIdx.x] = lo;
    }
    __syncthreads();
    int g = threadIdx.x >> 6;
    int n = blockIdx.x * 4 + g;
    int t = threadIdx.x & 63;
    const float4* H = (const float4*)Hout;
    const int* cols = g_col + (size_t)n * MAXDEG;
    int dn = g_deg[n];
    int hn = hd[g];
    float4 h = H[(size_t)n * 64 + t];
    float4 vs = make_float4(0.f, 0.f, 0.f, 0.f);
    int c = 0;
    for (; c + 2 <= hn; c += 2) {
        float4 v0 = H[(size_t)cols[c] * 64 + t];
        float4 v1 = H[(size_t)cols[c + 1] * 64 + t];
        vs.x += v0.x + v1.x; vs.y += v0.y + v1.y;
        vs.z += v0.z + v1.z; vs.w += v0.w + v1.w;
    }
    if (c < hn) {
        float4 v = H[(size_t)cols[c] * 64 + t];
        vs.x += v.x; vs.y += v.y; vs.z += v.z; vs.w += v.w;
    }
    float fd = (float)dn - 1.0f;
    float dot = fd * (h.x * h.x + h.y * h.y + h.z * h.z + h.w * h.w)
              - 2.0f * (h.x * vs.x + h.y * vs.y + h.z * vs.z + h.w * vs.w);
    dot = warpSum(dot);
    __shared__ float sred[8];
    if ((threadIdx.x & 31) == 0) sred[threadIdx.x >> 5] = dot;
    __syncthreads();
    if (threadIdx.x < 4)
        g_partials[blockIdx.x * 4 + threadIdx.x] =
            sred[threadIdx.x * 2] + sred[threadIdx.x * 2 + 1];

    __threadfence();
    __shared__ int isLast;
    if (threadIdx.x == 0) {
        int v = atomicAdd(&g_ctr, 1);
        isLast = (v == (int)gridDim.x - 1) ? 1 : 0;
        if (isLast) atomicExch(&g_ctr, 0);
    }
    __syncthreads();
    if (!isLast) return;
    __threadfence();

    float v = 0.f;
    for (int i = threadIdx.x; i < N; i += 256) v += g_partials[i];
    __shared__ float red2[256];
    red2[threadIdx.x] = v;
    __syncthreads();
    for (int off = 128; off > 0; off >>= 1) {
        if (threadIdx.x < off) red2[threadIdx.x] += red2[threadIdx.x + off];
        __syncthreads();
    }
    if (threadIdx.x == 0) {
        float orth = 0.f;
        for (int p = 0; p < 10; p++) orth += g_orth[p];
        float m = fmaxf(fmaxf(hw[0], hw[1]), fmaxf(hw[2], hw[3]));
        float e0 = expf(hw[0] - m), e1 = expf(hw[1] - m);
        float e2 = expf(hw[2] - m), e3 = expf(hw[3] - m);
        float s = e0 + e1 + e2 + e3;
        int base = N * D;
        if (base < out_size) out[base] = orth;
        if (base + 1 < out_size) out[base + 1] = red2[0];
        if (base + 2 < out_size) out[base + 2] = e0 / s;
        if (base + 3 < out_size) out[base + 3] = e1 / s;
        if (base + 4 < out_size) out[base + 4] = e2 / s;
        if (base + 5 < out_size) out[base + 5] = e3 / s;
    }
}

// ---------------- launch ----------------
extern "C" void kernel_launch(void* const* d_in, const int* in_sizes, int n_in,
                              void* d_out, int out_size) {
    const float* hops      = (const float*)d_in[0];
    const float* adj       = (const float*)d_in[1];
    const float* U         = (const float*)d_in[3];
    const float* hw        = (const float*)d_in[4];
    const float* threshold = (const float*)d_in[5];
    const float* lam       = (const float*)d_in[6];
    float* out = (float*)d_out;

    k_mega1<<<810, 256>>>(hops, adj, U, hw);
    k_gram<<<128, 1024>>>();
    {
        dim3 g(N / 32, K);
        k_MZ<<<g, 256>>>();
    }
    k_attn<<<(K * N) / 8, 256>>>();
    k_lapO<<<N / 8, 256>>>(lam);
    {
        dim3 g(N / 32, D / 32);
        k_HoutG<<<g, 256>>>(hops, threshold, out);
    }
    k_lapF<<<N / 4, 256>>>(out, hw, out, out_size);
}

// round 8
// speedup vs baseline: 4.6021x; 1.1104x over previous
#include <cuda_runtime.h>
#include <math.h>

#define K 4
#define N 4096
#define D 256
#define S 32
#define MAXDEG 512
#define ETA 0.5f
#define COEFF 0.03125f   // S/(N*EPS^2)

// ---------------- scratch ----------------
__device__ float g_Zt[K * N * S];        // [k][n][s]
__device__ float g_MZt[K * N * S];       // [k][n][s]
__device__ float g_Minv[K * S * S];
__device__ float g_O[(size_t)N * (K * S)];   // O_cat: [n][k*S+s]
__device__ float g_O2[(size_t)N * (K * S)];  // (I - lam*L) @ O_cat
__device__ float g_Wc[K * S * D];        // w_k * U[k]^T : [k*S+s][d]
__device__ float g_gramP[K * 32 * S * S];
__device__ int   g_col[(size_t)N * MAXDEG];
__device__ int   g_deg[N];
__device__ float g_partials[N];
__device__ float g_orth[10];
__device__ int   g_ctr;       // zero-init; self-resetting
__device__ int   g_ctrK[K];   // zero-init; self-resetting

__device__ __forceinline__ float warpSum(float v) {
    v += __shfl_xor_sync(0xffffffffu, v, 16);
    v += __shfl_xor_sync(0xffffffffu, v, 8);
    v += __shfl_xor_sync(0xffffffffu, v, 4);
    v += __shfl_xor_sync(0xffffffffu, v, 2);
    v += __shfl_xor_sync(0xffffffffu, v, 1);
    return v;
}

// ================= mega kernel 1: Z (0..255) | CSR (256..767) | Wc (768..799) | orth (800..809) =================
__global__ void __launch_bounds__(256) k_mega1(const float* __restrict__ hops,
                                               const float* __restrict__ adj,
                                               const float* __restrict__ U,
                                               const float* __restrict__ hw) {
    __shared__ float sm[6528];
    int bx = blockIdx.x;
    int tid = threadIdx.x;

    if (bx < 256) {
        // ---------- Z = hops[k] @ U[k] : 64n x 32s tile, double-buffered ----------
        int k = bx >> 6;
        int n0 = (bx & 63) * 64;
        float* hsT0 = sm;            // 32*66
        float* hsT1 = sm + 2112;
        float* us0  = sm + 4224;     // 32*36
        float* us1  = sm + 5376;
        int ny = tid >> 3;
        int sx = (tid & 7) * 4;
        int rowq = tid >> 3;
        int q = tid & 7;
        const float* Hb = hops + ((size_t)k * N + n0) * D;
        const float* Ub = U + (size_t)k * D * S;

        float4 h0, h1, u0;
        h0 = *(const float4*)&Hb[(size_t)rowq * D + q * 4];
        h1 = *(const float4*)&Hb[(size_t)(rowq + 32) * D + q * 4];
        u0 = *(const float4*)&Ub[(size_t)rowq * S + q * 4];
        {
            float* hb = hsT0;
            hb[(q * 4 + 0) * 66 + rowq] = h0.x;
            hb[(q * 4 + 1) * 66 + rowq] = h0.y;
            hb[(q * 4 + 2) * 66 + rowq] = h0.z;
            hb[(q * 4 + 3) * 66 + rowq] = h0.w;
            hb[(q * 4 + 0) * 66 + rowq + 32] = h1.x;
            hb[(q * 4 + 1) * 66 + rowq + 32] = h1.y;
            hb[(q * 4 + 2) * 66 + rowq + 32] = h1.z;
            hb[(q * 4 + 3) * 66 + rowq + 32] = h1.w;
            *(float4*)&us0[rowq * 36 + q * 4] = u0;
        }
        __syncthreads();

        float a0x = 0.f, a0y = 0.f, a0z = 0.f, a0w = 0.f;
        float a1x = 0.f, a1y = 0.f, a1z = 0.f, a1w = 0.f;

        for (int ch = 0; ch < 8; ch++) {
            const float* hb = (ch & 1) ? hsT1 : hsT0;
            const float* ub = (ch & 1) ? us1 : us0;
            if (ch < 7) {
                int dc = (ch + 1) * 32;
                h0 = *(const float4*)&Hb[(size_t)rowq * D + dc + q * 4];
                h1 = *(const float4*)&Hb[(size_t)(rowq + 32) * D + dc + q * 4];
                u0 = *(const float4*)&Ub[(size_t)(dc + rowq) * S + q * 4];
            }
#pragma unroll
            for (int d = 0; d < 32; d++) {
                float2 h = *(const float2*)&hb[d * 66 + ny * 2];
                float4 u = *(const float4*)&ub[d * 36 + sx];
                a0x += h.x * u.x; a0y += h.x * u.y; a0z += h.x * u.z; a0w += h.x * u.w;
                a1x += h.y * u.x; a1y += h.y * u.y; a1z += h.y * u.z; a1w += h.y * u.w;
            }
            if (ch < 7) {
                float* hb2 = (ch & 1) ? hsT0 : hsT1;
                float* ub2 = (ch & 1) ? us0 : us1;
                hb2[(q * 4 + 0) * 66 + rowq] = h0.x;
                hb2[(q * 4 + 1) * 66 + rowq] = h0.y;
                hb2[(q * 4 + 2) * 66 + rowq] = h0.z;
                hb2[(q * 4 + 3) * 66 + rowq] = h0.w;
                hb2[(q * 4 + 0) * 66 + rowq + 32] = h1.x;
                hb2[(q * 4 + 1) * 66 + rowq + 32] = h1.y;
                hb2[(q * 4 + 2) * 66 + rowq + 32] = h1.z;
                hb2[(q * 4 + 3) * 66 + rowq + 32] = h1.w;
                *(float4*)&ub2[rowq * 36 + q * 4] = u0;
            }
            __syncthreads();
        }
        size_t base = ((size_t)k * N + n0 + ny * 2) * S + sx;
        *(float4*)&g_Zt[base] = make_float4(a0x, a0y, a0z, a0w);
        *(float4*)&g_Zt[base + S] = make_float4(a1x, a1y, a1z, a1w);
    } else if (bx < 768) {
        // ---------- CSR build (warp per row, float4 + 4 ballots per 128 cols) ----------
        int n = (bx - 256) * 8 + (tid >> 5);
        int lane = tid & 31;
        const float4* row = (const float4*)(adj + (size_t)n * N);
        int* dst = g_col + (size_t)n * MAXDEG;
        unsigned lm = (1u << lane) - 1u;
        int cnt = 0;
        for (int base = 0; base < N / 4; base += 32) {
            float4 a = row[base + lane];
            unsigned m0 = __ballot_sync(0xffffffffu, a.x != 0.0f);
            unsigned m1 = __ballot_sync(0xffffffffu, a.y != 0.0f);
            unsigned m2 = __ballot_sync(0xffffffffu, a.z != 0.0f);
            unsigned m3 = __ballot_sync(0xffffffffu, a.w != 0.0f);
            int pre = cnt + __popc(m0 & lm) + __popc(m1 & lm)
                          + __popc(m2 & lm) + __popc(m3 & lm);
            int j0 = (base + lane) * 4;
            if (a.x != 0.0f) dst[pre] = j0;
            int o1 = pre + ((m0 >> lane) & 1);
            if (a.y != 0.0f) dst[o1] = j0 + 1;
            int o2 = o1 + ((m1 >> lane) & 1);
            if (a.z != 0.0f) dst[o2] = j0 + 2;
            int o3 = o2 + ((m2 >> lane) & 1);
            if (a.w != 0.0f) dst[o3] = j0 + 3;
            cnt += __popc(m0) + __popc(m1) + __popc(m2) + __popc(m3);
        }
        if (lane == 0) g_deg[n] = min(cnt, MAXDEG);
    } else if (bx < 800) {
        // ---------- Wc[k*S+s][d] = w_k * U[k][d][s] ----------
        float m = fmaxf(fmaxf(hw[0], hw[1]), fmaxf(hw[2], hw[3]));
        float e0 = expf(hw[0] - m), e1 = expf(hw[1] - m);
        float e2 = expf(hw[2] - m), e3 = expf(hw[3] - m);
        float sum = e0 + e1 + e2 + e3;
        int base = ((bx - 768) * 256 + tid) * 4;
        float4 u4 = *(const float4*)&U[base];
        int k = base / (D * S);
        int rem = base % (D * S);
        int d = rem / S;
        int s = rem % S;
        float wk = (k == 0 ? e0 : k == 1 ? e1 : k == 2 ? e2 : e3) / sum;
        g_Wc[(k * S + s + 0) * D + d] = wk * u4.x;
        g_Wc[(k * S + s + 1) * D + d] = wk * u4.y;
        g_Wc[(k * S + s + 2) * D + d] = wk * u4.z;
        g_Wc[(k * S + s + 3) * D + d] = wk * u4.w;
    } else {
        // ---------- orth pair (s,t) dots; 4 t per thread ----------
        const int kk[10] = {0, 0, 0, 0, 1, 1, 1, 2, 2, 3};
        const int ll[10] = {0, 1, 2, 3, 1, 2, 3, 2, 3, 3};
        int p = bx - 800;
        int k = kk[p], l = ll[p];
        int s = tid >> 3;
        int t0 = (tid & 7) * 4;
        float* uk = sm;
        float* ul = sm + 2048;
        float* red = sm + 4096;
        float c0 = 0.f, c1 = 0.f, c2 = 0.f, c3 = 0.f;
        for (int dc = 0; dc < D; dc += 64) {
            for (int i = tid; i < 2048; i += 256) {
                uk[i] = U[((size_t)k * D + dc) * S + i];
                ul[i] = U[((size_t)l * D + dc) * S + i];
            }
            __syncthreads();
#pragma unroll 8
            for (int d = 0; d < 64; d++) {
                float a = uk[d * 32 + s];
                float4 b = *(const float4*)&ul[d * 32 + t0];
                c0 += a * b.x; c1 += a * b.y; c2 += a * b.z; c3 += a * b.w;
            }
            __syncthreads();
        }
        if (k == l) {
            if (s == t0 + 0) c0 -= 1.0f;
            if (s == t0 + 1) c1 -= 1.0f;
            if (s == t0 + 2) c2 -= 1.0f;
            if (s == t0 + 3) c3 -= 1.0f;
        }
        red[tid] = (c0 * c0 + c1 * c1) + (c2 * c2 + c3 * c3);
        __syncthreads();
        for (int off = 128; off > 0; off >>= 1) {
            if (tid < off) red[tid] += red[tid + off];
            __syncthreads();
        }
        if (tid == 0) g_orth[p] = red[0];
    }
}

// ================= gram partials + last-block-per-k inversion =================
__global__ void __launch_bounds__(1024) k_gram(void) {
    __shared__ float sm[4224];
    int tid = threadIdx.x;
    int k = blockIdx.x >> 5;
    int chunk = blockIdx.x & 31;
    float* zs = sm;
    const float4* Z4 = (const float4*)(g_Zt + ((size_t)k * N + chunk * 128) * S);
    ((float4*)zs)[tid] = Z4[tid];
    __syncthreads();
    int s = tid >> 5, t = tid & 31;
    float g0 = 0.f, g1 = 0.f, g2 = 0.f, g3 = 0.f;
#pragma unroll 8
    for (int n = 0; n < 128; n += 4) {
        g0 += zs[(n + 0) * 32 + s] * zs[(n + 0) * 32 + t];
        g1 += zs[(n + 1) * 32 + s] * zs[(n + 1) * 32 + t];
        g2 += zs[(n + 2) * 32 + s] * zs[(n + 2) * 32 + t];
        g3 += zs[(n + 3) * 32 + s] * zs[(n + 3) * 32 + t];
    }
    g_gramP[(((size_t)k * 32 + chunk) * S + s) * S + t] = (g0 + g1) + (g2 + g3);
    __threadfence();
    __shared__ int isLast;
    if (tid == 0) {
        int v = atomicAdd(&g_ctrK[k], 1);
        isLast = (v == 31);
        if (v == 31) atomicExch(&g_ctrK[k], 0);
    }
    __syncthreads();
    if (!isLast) return;
    __threadfence();
    float g = 0.f;
    for (int c = 0; c < 32; c++)
        g += g_gramP[(((size_t)k * 32 + c) * S + s) * S + t];
    float (*aug)[66] = (float(*)[66])sm;
    __syncthreads();
    aug[s][t] = (s == t ? 1.0f : 0.0f) + COEFF * g;
    aug[s][32 + t] = (s == t ? 1.0f : 0.0f);
    __syncthreads();
    int r0 = tid >> 6, c0 = tid & 63;
    int tid2 = tid + 1024;
    int r1 = tid2 >> 6, c1 = tid2 & 63;
    for (int p = 0; p < 32; p++) {
        float inv = 1.0f / aug[p][p];
        float f0 = aug[r0][p], pr0 = aug[p][c0];
        float f1 = aug[r1][p], pr1 = aug[p][c1];
        __syncthreads();
        if (r0 == p) aug[p][c0] = pr0 * inv;
        else         aug[r0][c0] -= f0 * inv * pr0;
        if (r1 == p) aug[p][c1] = pr1 * inv;
        else         aug[r1][c1] -= f1 * inv * pr1;
        __syncthreads();
    }
    g_Minv[k * S * S + s * S + t] = aug[s][32 + t];
}

// ================= MZt = Minv[k] @ Zt rows : conflict-free, 4 rows/warp =================
__global__ void k_MZ(void) {
    __shared__ float Msh[32 * 33];
    __shared__ float zsh[32 * 33];
    int k = blockIdx.y;
    int n0 = blockIdx.x * 32;
    int tid = threadIdx.x;
    int w = tid >> 5;
    int lane = tid & 31;
    {
        float4 v = ((const float4*)(g_Minv + k * S * S))[tid];
        int r = (tid * 4) >> 5;
        int c = (tid * 4) & 31;
        float* dst = &Msh[r * 33 + c];
        dst[0] = v.x; dst[1] = v.y; dst[2] = v.z; dst[3] = v.w;
    }
    {
        int r = tid >> 3, q = tid & 7;
        float4 v = *(const float4*)&g_Zt[((size_t)k * N + n0 + r) * S + q * 4];
        float* dst = &zsh[r * 33 + q * 4];
        dst[0] = v.x; dst[1] = v.y; dst[2] = v.z; dst[3] = v.w;
    }
    __syncthreads();
    float a0 = 0.f, a1 = 0.f, a2 = 0.f, a3 = 0.f;
    const float* z0 = &zsh[(w * 4 + 0) * 33];
    const float* z1 = &zsh[(w * 4 + 1) * 33];
    const float* z2 = &zsh[(w * 4 + 2) * 33];
    const float* z3 = &zsh[(w * 4 + 3) * 33];
#pragma unroll
    for (int t = 0; t < 32; t++) {
        float mv = Msh[t * 33 + lane];
        a0 += mv * z0[t];
        a1 += mv * z1[t];
        a2 += mv * z2[t];
        a3 += mv * z3[t];
    }
    size_t base = ((size_t)k * N + n0 + w * 4) * S + lane;
    g_MZt[base] = a0;
    g_MZt[base + S] = a1;
    g_MZt[base + 2 * S] = a2;
    g_MZt[base + 3 * S] = a3;
}

// ================= sparse attention: register-resident, zero smem =================
// lane = rr*? decomposition: f = lane&7 (quad index), rr = lane>>3 (row group 0..3).
// Per step: one coalesced LDG.128 brings quad f of rows 4*pss+rr; score via
// 3-butterfly over f-lanes; p*v accumulated in registers; rr-groups folded at end.
__global__ void __launch_bounds__(256) k_attn(void) {
    int w = threadIdx.x >> 5;
    int lane = threadIdx.x & 31;
    int gwarp = blockIdx.x * 8 + w;
    int k = gwarp >> 12;
    int n = gwarp & (N - 1);
    const float* MZ = g_MZt + (size_t)k * N * S;
    const int* cols = g_col + (size_t)n * MAXDEG;
    int dn = g_deg[n];
    int f = lane & 7;
    int rr = lane >> 3;
    // q quad for this lane (row n of Zt)
    float4 qq = *(const float4*)&g_Zt[((size_t)k * N + n) * S + f * 4];
    float4 acc = make_float4(0.f, 0.f, 0.f, 0.f);
    float l = 0.f;

    for (int c0 = 0; c0 < dn; c0 += 32) {
        int j = (c0 + lane < dn) ? cols[c0 + lane] : 0;
#pragma unroll
        for (int pss = 0; pss < 8; pss++) {
            int row = pss * 4 + rr;
            int jr = __shfl_sync(0xffffffffu, j, row);
            float4 vv = *(const float4*)&MZ[(size_t)jr * S + f * 4];
            float part = qq.x * vv.x + qq.y * vv.y + qq.z * vv.z + qq.w * vv.w;
            part += __shfl_xor_sync(0xffffffffu, part, 1);
            part += __shfl_xor_sync(0xffffffffu, part, 2);
            part += __shfl_xor_sync(0xffffffffu, part, 4);
            float p = (c0 + row < dn) ? __expf(part) : 0.f;
            l += p;
            acc.x += p * vv.x; acc.y += p * vv.y;
            acc.z += p * vv.z; acc.w += p * vv.w;
        }
    }
    // fold rr groups (xor 8, 16)
    acc.x += __shfl_xor_sync(0xffffffffu, acc.x, 8);
    acc.y += __shfl_xor_sync(0xffffffffu, acc.y, 8);
    acc.z += __shfl_xor_sync(0xffffffffu, acc.z, 8);
    acc.w += __shfl_xor_sync(0xffffffffu, acc.w, 8);
    l     += __shfl_xor_sync(0xffffffffu, l, 8);
    acc.x += __shfl_xor_sync(0xffffffffu, acc.x, 16);
    acc.y += __shfl_xor_sync(0xffffffffu, acc.y, 16);
    acc.z += __shfl_xor_sync(0xffffffffu, acc.z, 16);
    acc.w += __shfl_xor_sync(0xffffffffu, acc.w, 16);
    l     += __shfl_xor_sync(0xffffffffu, l, 16);
    if (rr == 0) {
        float inv = 1.0f / l;
        *(float4*)&g_O[(size_t)n * (K * S) + k * S + f * 4] =
            make_float4(acc.x * inv, acc.y * inv, acc.z * inv, acc.w * inv);
    }
}

// ================= O2 = (I - lam*L) @ O_cat =================
__global__ void k_lapO(const float* __restrict__ lambda_lap) {
    int n = blockIdx.x * 8 + (threadIdx.x >> 5);
    int lane = threadIdx.x & 31;
    const float4* O = (const float4*)g_O;
    const int* cols = g_col + (size_t)n * MAXDEG;
    int dn = g_deg[n];
    float4 o = O[(size_t)n * 32 + lane];
    float4 s = make_float4(0.f, 0.f, 0.f, 0.f);
    int c = 0;
    for (; c + 2 <= dn; c += 2) {
        float4 v0 = O[(size_t)cols[c] * 32 + lane];
        float4 v1 = O[(size_t)cols[c + 1] * 32 + lane];
        s.x += v0.x + v1.x; s.y += v0.y + v1.y;
        s.z += v0.z + v1.z; s.w += v0.w + v1.w;
    }
    if (c < dn) {
        float4 v = O[(size_t)cols[c] * 32 + lane];
        s.x += v.x; s.y += v.y; s.z += v.z; s.w += v.w;
    }
    float lam = lambda_lap[0];
    float fd = (float)dn;
    float4 r;
    r.x = o.x - lam * (fd * o.x - s.x);
    r.y = o.y - lam * (fd * o.y - s.y);
    r.z = o.z - lam * (fd * o.z - s.z);
    r.w = o.w - lam * (fd * o.w - s.w);
    ((float4*)g_O2)[(size_t)n * 32 + lane] = r;
}

// ================= H_out = softthresh(hops0 + ETA * O2 @ Wc) =================
__global__ void k_HoutG(const float* __restrict__ hops,
                        const float* __restrict__ threshold,
                        float* __restrict__ out) {
    __shared__ float as[32][33];
    __shared__ float ws[32][33];
    int n0 = blockIdx.x * 32, d0 = blockIdx.y * 32;
    int lane = threadIdx.x & 31;
    int row = threadIdx.x >> 5;
    float acc[4] = {0.f, 0.f, 0.f, 0.f};
    for (int cc = 0; cc < K * S; cc += 32) {
#pragma unroll
        for (int i = 0; i < 4; i++) {
            int r = row + i * 8;
            as[r][lane] = g_O2[(size_t)(n0 + r) * (K * S) + cc + lane];
            ws[r][lane] = g_Wc[(size_t)(cc + r) * D + d0 + lane];
        }
        __syncthreads();
#pragma unroll
        for (int dd = 0; dd < 32; dd++) {
            float wv = ws[dd][lane];
#pragma unroll
            for (int i = 0; i < 4; i++) acc[i] += as[row * 4 + i][dd] * wv;
        }
        __syncthreads();
    }
    float th = threshold[d0 + lane];
#pragma unroll
    for (int i = 0; i < 4; i++) {
        int n = n0 + row * 4 + i;
        float hh = hops[(size_t)n * D + d0 + lane] + ETA * acc[i];
        float ab = fabsf(hh) - th;
        out[(size_t)n * D + d0 + lane] = (ab > 0.f) ? copysignf(ab, hh) : 0.f;
    }
}

// ================= lap_smooth partials (symmetric half) + fused final =================
__global__ void k_lapF(const float* __restrict__ Hout, const float* __restrict__ hw,
                       float* __restrict__ out, int out_size) {
    __shared__ int hd[4];
    if (threadIdx.x < 4) {
        int nn = blockIdx.x * 4 + threadIdx.x;
        const int* cc = g_col + (size_t)nn * MAXDEG;
        int lo = 0, hi = g_deg[nn];
        while (lo < hi) {
            int mid = (lo + hi) >> 1;
            if (cc[mid] < nn) lo = mid + 1; else hi = mid;
        }
        hd[threadIdx.x] = lo;
    }
    __syncthreads();
    int g = threadIdx.x >> 6;
    int n = blockIdx.x * 4 + g;
    int t = threadIdx.x & 63;
    const float4* H = (const float4*)Hout;
    const int* cols = g_col + (size_t)n * MAXDEG;
    int dn = g_deg[n];
    int hn = hd[g];
    float4 h = H[(size_t)n * 64 + t];
    float4 vs = make_float4(0.f, 0.f, 0.f, 0.f);
    int c = 0;
    for (; c + 2 <= hn; c += 2) {
        float4 v0 = H[(size_t)cols[c] * 64 + t];
        float4 v1 = H[(size_t)cols[c + 1] * 64 + t];
        vs.x += v0.x + v1.x; vs.y += v0.y + v1.y;
        vs.z += v0.z + v1.z; vs.w += v0.w + v1.w;
    }
    if (c < hn) {
        float4 v = H[(size_t)cols[c] * 64 + t];
        vs.x += v.x; vs.y += v.y; vs.z += v.z; vs.w += v.w;
    }
    float fd = (float)dn - 1.0f;
    float dot = fd * (h.x * h.x + h.y * h.y + h.z * h.z + h.w * h.w)
              - 2.0f * (h.x * vs.x + h.y * vs.y + h.z * vs.z + h.w * vs.w);
    dot = warpSum(dot);
    __shared__ float sred[8];
    if ((threadIdx.x & 31) == 0) sred[threadIdx.x >> 5] = dot;
    __syncthreads();
    if (threadIdx.x < 4)
        g_partials[blockIdx.x * 4 + threadIdx.x] =
            sred[threadIdx.x * 2] + sred[threadIdx.x * 2 + 1];

    __threadfence();
    __shared__ int isLast;
    if (threadIdx.x == 0) {
        int v = atomicAdd(&g_ctr, 1);
        isLast = (v == (int)gridDim.x - 1) ? 1 : 0;
        if (isLast) atomicExch(&g_ctr, 0);
    }
    __syncthreads();
    if (!isLast) return;
    __threadfence();

    float v = 0.f;
    for (int i = threadIdx.x; i < N; i += 256) v += g_partials[i];
    __shared__ float red2[256];
    red2[threadIdx.x] = v;
    __syncthreads();
    for (int off = 128; off > 0; off >>= 1) {
        if (threadIdx.x < off) red2[threadIdx.x] += red2[threadIdx.x + off];
        __syncthreads();
    }
    if (threadIdx.x == 0) {
        float orth = 0.f;
        for (int p = 0; p < 10; p++) orth += g_orth[p];
        float m = fmaxf(fmaxf(hw[0], hw[1]), fmaxf(hw[2], hw[3]));
        float e0 = expf(hw[0] - m), e1 = expf(hw[1] - m);
        float e2 = expf(hw[2] - m), e3 = expf(hw[3] - m);
        float s = e0 + e1 + e2 + e3;
        int base = N * D;
        if (base < out_size) out[base] = orth;
        if (base + 1 < out_size) out[base + 1] = red2[0];
        if (base + 2 < out_size) out[base + 2] = e0 / s;
        if (base + 3 < out_size) out[base + 3] = e1 / s;
        if (base + 4 < out_size) out[base + 4] = e2 / s;
        if (base + 5 < out_size) out[base + 5] = e3 / s;
    }
}

// ---------------- launch ----------------
extern "C" void kernel_launch(void* const* d_in, const int* in_sizes, int n_in,
                              void* d_out, int out_size) {
    const float* hops      = (const float*)d_in[0];
    const float* adj       = (const float*)d_in[1];
    const float* U         = (const float*)d_in[3];
    const float* hw        = (const float*)d_in[4];
    const float* threshold = (const float*)d_in[5];
    const float* lam       = (const float*)d_in[6];
    float* out = (float*)d_out;

    k_mega1<<<810, 256>>>(hops, adj, U, hw);
    k_gram<<<128, 1024>>>();
    {
        dim3 g(N / 32, K);
        k_MZ<<<g, 256>>>();
    }
    k_attn<<<(K * N) / 8, 256>>>();
    k_lapO<<<N / 8, 256>>>(lam);
    {
        dim3 g(N / 32, D / 32);
        k_HoutG<<<g, 256>>>(hops, threshold, out);
    }
    k_lapF<<<N / 4, 256>>>(out, hw, out, out_size);
}

// round 9
// speedup vs baseline: 4.6175x; 1.0033x over previous
#include <cuda_runtime.h>
#include <math.h>

#define K 4
#define N 4096
#define D 256
#define S 32
#define MAXDEG 512
#define ETA 0.5f
#define COEFF 0.03125f   // S/(N*EPS^2)

// ---------------- scratch ----------------
__device__ float g_Zt[K * N * S];        // [k][n][s]
__device__ float g_MZt[K * N * S];       // [k][n][s]
__device__ float g_Minv[K * S * S];
__device__ float g_O[(size_t)N * (K * S)];   // O_cat: [n][k*S+s]
__device__ float g_O2[(size_t)N * (K * S)];  // (I - lam*L) @ O_cat
__device__ float g_Wc[K * S * D];        // w_k * U[k]^T : [k*S+s][d]
__device__ float g_gramP[K * 32 * S * S];
__device__ int   g_col[(size_t)N * MAXDEG];
__device__ int   g_deg[N];
__device__ float g_partials[N];
__device__ float g_orth[10];
__device__ int   g_ctr;       // zero-init; self-resetting
__device__ int   g_ctrK[K];   // zero-init; self-resetting

__device__ __forceinline__ float warpSum(float v) {
    v += __shfl_xor_sync(0xffffffffu, v, 16);
    v += __shfl_xor_sync(0xffffffffu, v, 8);
    v += __shfl_xor_sync(0xffffffffu, v, 4);
    v += __shfl_xor_sync(0xffffffffu, v, 2);
    v += __shfl_xor_sync(0xffffffffu, v, 1);
    return v;
}

// ================= mega kernel 1: Z (0..255) | CSR (256..767) | Wc (768..799) | orth (800..809) =================
__global__ void __launch_bounds__(256) k_mega1(const float* __restrict__ hops,
                                               const float* __restrict__ adj,
                                               const float* __restrict__ U,
                                               const float* __restrict__ hw) {
    __shared__ float sm[6528];
    int bx = blockIdx.x;
    int tid = threadIdx.x;

    if (bx < 256) {
        // ---------- Z = hops[k] @ U[k] : 64n x 32s tile, double-buffered ----------
        int k = bx >> 6;
        int n0 = (bx & 63) * 64;
        float* hsT0 = sm;            // 32*66
        float* hsT1 = sm + 2112;
        float* us0  = sm + 4224;     // 32*36
        float* us1  = sm + 5376;
        int ny = tid >> 3;
        int sx = (tid & 7) * 4;
        int rowq = tid >> 3;
        int q = tid & 7;
        const float* Hb = hops + ((size_t)k * N + n0) * D;
        const float* Ub = U + (size_t)k * D * S;

        float4 h0, h1, u0;
        h0 = *(const float4*)&Hb[(size_t)rowq * D + q * 4];
        h1 = *(const float4*)&Hb[(size_t)(rowq + 32) * D + q * 4];
        u0 = *(const float4*)&Ub[(size_t)rowq * S + q * 4];
        {
            float* hb = hsT0;
            hb[(q * 4 + 0) * 66 + rowq] = h0.x;
            hb[(q * 4 + 1) * 66 + rowq] = h0.y;
            hb[(q * 4 + 2) * 66 + rowq] = h0.z;
            hb[(q * 4 + 3) * 66 + rowq] = h0.w;
            hb[(q * 4 + 0) * 66 + rowq + 32] = h1.x;
            hb[(q * 4 + 1) * 66 + rowq + 32] = h1.y;
            hb[(q * 4 + 2) * 66 + rowq + 32] = h1.z;
            hb[(q * 4 + 3) * 66 + rowq + 32] = h1.w;
            *(float4*)&us0[rowq * 36 + q * 4] = u0;
        }
        __syncthreads();

        float a0x = 0.f, a0y = 0.f, a0z = 0.f, a0w = 0.f;
        float a1x = 0.f, a1y = 0.f, a1z = 0.f, a1w = 0.f;

        for (int ch = 0; ch < 8; ch++) {
            const float* hb = (ch & 1) ? hsT1 : hsT0;
            const float* ub = (ch & 1) ? us1 : us0;
            if (ch < 7) {
                int dc = (ch + 1) * 32;
                h0 = *(const float4*)&Hb[(size_t)rowq * D + dc + q * 4];
                h1 = *(const float4*)&Hb[(size_t)(rowq + 32) * D + dc + q * 4];
                u0 = *(const float4*)&Ub[(size_t)(dc + rowq) * S + q * 4];
            }
#pragma unroll
            for (int d = 0; d < 32; d++) {
                float2 h = *(const float2*)&hb[d * 66 + ny * 2];
                float4 u = *(const float4*)&ub[d * 36 + sx];
                a0x += h.x * u.x; a0y += h.x * u.y; a0z += h.x * u.z; a0w += h.x * u.w;
                a1x += h.y * u.x; a1y += h.y * u.y; a1z += h.y * u.z; a1w += h.y * u.w;
            }
            if (ch < 7) {
                float* hb2 = (ch & 1) ? hsT0 : hsT1;
                float* ub2 = (ch & 1) ? us0 : us1;
                hb2[(q * 4 + 0) * 66 + rowq] = h0.x;
                hb2[(q * 4 + 1) * 66 + rowq] = h0.y;
                hb2[(q * 4 + 2) * 66 + rowq] = h0.z;
                hb2[(q * 4 + 3) * 66 + rowq] = h0.w;
                hb2[(q * 4 + 0) * 66 + rowq + 32] = h1.x;
                hb2[(q * 4 + 1) * 66 + rowq + 32] = h1.y;
                hb2[(q * 4 + 2) * 66 + rowq + 32] = h1.z;
                hb2[(q * 4 + 3) * 66 + rowq + 32] = h1.w;
                *(float4*)&ub2[rowq * 36 + q * 4] = u0;
            }
            __syncthreads();
        }
        size_t base = ((size_t)k * N + n0 + ny * 2) * S + sx;
        *(float4*)&g_Zt[base] = make_float4(a0x, a0y, a0z, a0w);
        *(float4*)&g_Zt[base + S] = make_float4(a1x, a1y, a1z, a1w);
    } else if (bx < 768) {
        // ---------- CSR build (warp per row, float4 + 4 ballots per 128 cols) ----------
        int n = (bx - 256) * 8 + (tid >> 5);
        int lane = tid & 31;
        const float4* row = (const float4*)(adj + (size_t)n * N);
        int* dst = g_col + (size_t)n * MAXDEG;
        unsigned lm = (1u << lane) - 1u;
        int cnt = 0;
        for (int base = 0; base < N / 4; base += 32) {
            float4 a = row[base + lane];
            unsigned m0 = __ballot_sync(0xffffffffu, a.x != 0.0f);
            unsigned m1 = __ballot_sync(0xffffffffu, a.y != 0.0f);
            unsigned m2 = __ballot_sync(0xffffffffu, a.z != 0.0f);
            unsigned m3 = __ballot_sync(0xffffffffu, a.w != 0.0f);
            int pre = cnt + __popc(m0 & lm) + __popc(m1 & lm)
                          + __popc(m2 & lm) + __popc(m3 & lm);
            int j0 = (base + lane) * 4;
            if (a.x != 0.0f) dst[pre] = j0;
            int o1 = pre + ((m0 >> lane) & 1);
            if (a.y != 0.0f) dst[o1] = j0 + 1;
            int o2 = o1 + ((m1 >> lane) & 1);
            if (a.z != 0.0f) dst[o2] = j0 + 2;
            int o3 = o2 + ((m2 >> lane) & 1);
            if (a.w != 0.0f) dst[o3] = j0 + 3;
            cnt += __popc(m0) + __popc(m1) + __popc(m2) + __popc(m3);
        }
        if (lane == 0) g_deg[n] = min(cnt, MAXDEG);
    } else if (bx < 800) {
        // ---------- Wc[k*S+s][d] = w_k * U[k][d][s] ----------
        float m = fmaxf(fmaxf(hw[0], hw[1]), fmaxf(hw[2], hw[3]));
        float e0 = expf(hw[0] - m), e1 = expf(hw[1] - m);
        float e2 = expf(hw[2] - m), e3 = expf(hw[3] - m);
        float sum = e0 + e1 + e2 + e3;
        int base = ((bx - 768) * 256 + tid) * 4;
        float4 u4 = *(const float4*)&U[base];
        int k = base / (D * S);
        int rem = base % (D * S);
        int d = rem / S;
        int s = rem % S;
        float wk = (k == 0 ? e0 : k == 1 ? e1 : k == 2 ? e2 : e3) / sum;
        g_Wc[(k * S + s + 0) * D + d] = wk * u4.x;
        g_Wc[(k * S + s + 1) * D + d] = wk * u4.y;
        g_Wc[(k * S + s + 2) * D + d] = wk * u4.z;
        g_Wc[(k * S + s + 3) * D + d] = wk * u4.w;
    } else {
        // ---------- orth pair (s,t) dots; 4 t per thread ----------
        const int kk[10] = {0, 0, 0, 0, 1, 1, 1, 2, 2, 3};
        const int ll[10] = {0, 1, 2, 3, 1, 2, 3, 2, 3, 3};
        int p = bx - 800;
        int k = kk[p], l = ll[p];
        int s = tid >> 3;
        int t0 = (tid & 7) * 4;
        float* uk = sm;
        float* ul = sm + 2048;
        float* red = sm + 4096;
        float c0 = 0.f, c1 = 0.f, c2 = 0.f, c3 = 0.f;
        for (int dc = 0; dc < D; dc += 64) {
            for (int i = tid; i < 2048; i += 256) {
                uk[i] = U[((size_t)k * D + dc) * S + i];
                ul[i] = U[((size_t)l * D + dc) * S + i];
            }
            __syncthreads();
#pragma unroll 8
            for (int d = 0; d < 64; d++) {
                float a = uk[d * 32 + s];
                float4 b = *(const float4*)&ul[d * 32 + t0];
                c0 += a * b.x; c1 += a * b.y; c2 += a * b.z; c3 += a * b.w;
            }
            __syncthreads();
        }
        if (k == l) {
            if (s == t0 + 0) c0 -= 1.0f;
            if (s == t0 + 1) c1 -= 1.0f;
            if (s == t0 + 2) c2 -= 1.0f;
            if (s == t0 + 3) c3 -= 1.0f;
        }
        red[tid] = (c0 * c0 + c1 * c1) + (c2 * c2 + c3 * c3);
        __syncthreads();
        for (int off = 128; off > 0; off >>= 1) {
            if (tid < off) red[tid] += red[tid + off];
            __syncthreads();
        }
        if (tid == 0) g_orth[p] = red[0];
    }
}

// ================= gram partials + last-block-per-k inversion =================
__global__ void __launch_bounds__(1024) k_gram(void) {
    __shared__ float sm[4224];
    int tid = threadIdx.x;
    int k = blockIdx.x >> 5;
    int chunk = blockIdx.x & 31;
    float* zs = sm;
    const float4* Z4 = (const float4*)(g_Zt + ((size_t)k * N + chunk * 128) * S);
    ((float4*)zs)[tid] = Z4[tid];
    __syncthreads();
    int s = tid >> 5, t = tid & 31;
    float g0 = 0.f, g1 = 0.f, g2 = 0.f, g3 = 0.f;
#pragma unroll 8
    for (int n = 0; n < 128; n += 4) {
        g0 += zs[(n + 0) * 32 + s] * zs[(n + 0) * 32 + t];
        g1 += zs[(n + 1) * 32 + s] * zs[(n + 1) * 32 + t];
        g2 += zs[(n + 2) * 32 + s] * zs[(n + 2) * 32 + t];
        g3 += zs[(n + 3) * 32 + s] * zs[(n + 3) * 32 + t];
    }
    g_gramP[(((size_t)k * 32 + chunk) * S + s) * S + t] = (g0 + g1) + (g2 + g3);
    __threadfence();
    __shared__ int isLast;
    if (tid == 0) {
        int v = atomicAdd(&g_ctrK[k], 1);
        isLast = (v == 31);
        if (v == 31) atomicExch(&g_ctrK[k], 0);
    }
    __syncthreads();
    if (!isLast) return;
    __threadfence();
    float g = 0.f;
    for (int c = 0; c < 32; c++)
        g += g_gramP[(((size_t)k * 32 + c) * S + s) * S + t];
    float (*aug)[66] = (float(*)[66])sm;
    __syncthreads();
    aug[s][t] = (s == t ? 1.0f : 0.0f) + COEFF * g;
    aug[s][32 + t] = (s == t ? 1.0f : 0.0f);
    __syncthreads();
    int r0 = tid >> 6, c0 = tid & 63;
    int tid2 = tid + 1024;
    int r1 = tid2 >> 6, c1 = tid2 & 63;
    for (int p = 0; p < 32; p++) {
        float inv = 1.0f / aug[p][p];
        float f0 = aug[r0][p], pr0 = aug[p][c0];
        float f1 = aug[r1][p], pr1 = aug[p][c1];
        __syncthreads();
        if (r0 == p) aug[p][c0] = pr0 * inv;
        else         aug[r0][c0] -= f0 * inv * pr0;
        if (r1 == p) aug[p][c1] = pr1 * inv;
        else         aug[r1][c1] -= f1 * inv * pr1;
        __syncthreads();
    }
    g_Minv[k * S * S + s * S + t] = aug[s][32 + t];
}

// ================= MZt = Minv[k] @ Zt rows : conflict-free, 4 rows/warp =================
__global__ void k_MZ(void) {
    __shared__ float Msh[32 * 33];
    __shared__ float zsh[32 * 33];
    int k = blockIdx.y;
    int n0 = blockIdx.x * 32;
    int tid = threadIdx.x;
    int w = tid >> 5;
    int lane = tid & 31;
    {
        float4 v = ((const float4*)(g_Minv + k * S * S))[tid];
        int r = (tid * 4) >> 5;
        int c = (tid * 4) & 31;
        float* dst = &Msh[r * 33 + c];
        dst[0] = v.x; dst[1] = v.y; dst[2] = v.z; dst[3] = v.w;
    }
    {
        int r = tid >> 3, q = tid & 7;
        float4 v = *(const float4*)&g_Zt[((size_t)k * N + n0 + r) * S + q * 4];
        float* dst = &zsh[r * 33 + q * 4];
        dst[0] = v.x; dst[1] = v.y; dst[2] = v.z; dst[3] = v.w;
    }
    __syncthreads();
    float a0 = 0.f, a1 = 0.f, a2 = 0.f, a3 = 0.f;
    const float* z0 = &zsh[(w * 4 + 0) * 33];
    const float* z1 = &zsh[(w * 4 + 1) * 33];
    const float* z2 = &zsh[(w * 4 + 2) * 33];
    const float* z3 = &zsh[(w * 4 + 3) * 33];
#pragma unroll
    for (int t = 0; t < 32; t++) {
        float mv = Msh[t * 33 + lane];
        a0 += mv * z0[t];
        a1 += mv * z1[t];
        a2 += mv * z2[t];
        a3 += mv * z3[t];
    }
    size_t base = ((size_t)k * N + n0 + w * 4) * S + lane;
    g_MZt[base] = a0;
    g_MZt[base + S] = a1;
    g_MZt[base + 2 * S] = a2;
    g_MZt[base + 3 * S] = a3;
}

// ================= sparse attention: 4 lanes/row, 8 rows/pass, 2-way ILP =================
// lane = (rr = lane>>2 in 0..7 : row group, f2 = lane&3 : 8-float segment).
// Per 8 edges: 1 broadcast col-LDG + 2 LDG.128 + 8 score FFMA + 2-level butterfly
// + 1 MUFU.EX2 (q pre-scaled by log2 e) + 8 acc FFMA  ~= 3.2 instr/edge.
__global__ void __launch_bounds__(256) k_attn(void) {
    int w = threadIdx.x >> 5;
    int lane = threadIdx.x & 31;
    int gwarp = blockIdx.x * 8 + w;
    int k = gwarp >> 12;
    int n = gwarp & (N - 1);
    const float* __restrict__ MZ = g_MZt + (size_t)k * N * S;
    const int* __restrict__ cols = g_col + (size_t)n * MAXDEG;
    int dn = g_deg[n];
    int f2 = lane & 3;
    int rr = lane >> 2;
    const float LOG2E = 1.4426950408889634f;
    const float* qp = &g_Zt[((size_t)k * N + n) * S + f2 * 8];
    float4 qa = *(const float4*)&qp[0];
    float4 qb = *(const float4*)&qp[4];
    qa.x *= LOG2E; qa.y *= LOG2E; qa.z *= LOG2E; qa.w *= LOG2E;
    qb.x *= LOG2E; qb.y *= LOG2E; qb.z *= LOG2E; qb.w *= LOG2E;

    float4 aa = make_float4(0.f, 0.f, 0.f, 0.f);
    float4 ab = make_float4(0.f, 0.f, 0.f, 0.f);
    float l = 0.f;

    for (int c0 = 0; c0 < dn; c0 += 16) {
        int r0 = c0 + rr;
        int r1 = c0 + 8 + rr;
        int j0 = (r0 < dn) ? cols[r0] : 0;
        int j1 = (r1 < dn) ? cols[r1] : 0;
        const float* vp0 = &MZ[(size_t)j0 * S + f2 * 8];
        const float* vp1 = &MZ[(size_t)j1 * S + f2 * 8];
        float4 va0 = *(const float4*)&vp0[0];
        float4 vb0 = *(const float4*)&vp0[4];
        float4 va1 = *(const float4*)&vp1[0];
        float4 vb1 = *(const float4*)&vp1[4];

        float p0 = qa.x * va0.x + qa.y * va0.y + qa.z * va0.z + qa.w * va0.w
                 + qb.x * vb0.x + qb.y * vb0.y + qb.z * vb0.z + qb.w * vb0.w;
        float p1 = qa.x * va1.x + qa.y * va1.y + qa.z * va1.z + qa.w * va1.w
                 + qb.x * vb1.x + qb.y * vb1.y + qb.z * vb1.z + qb.w * vb1.w;
        p0 += __shfl_xor_sync(0xffffffffu, p0, 1);
        p1 += __shfl_xor_sync(0xffffffffu, p1, 1);
        p0 += __shfl_xor_sync(0xffffffffu, p0, 2);
        p1 += __shfl_xor_sync(0xffffffffu, p1, 2);
        p0 = (r0 < dn) ? p0 : -1e30f;
        p1 = (r1 < dn) ? p1 : -1e30f;
        float e0 = exp2f(p0);
        float e1 = exp2f(p1);
        l += e0 + e1;
        aa.x += e0 * va0.x; aa.y += e0 * va0.y; aa.z += e0 * va0.z; aa.w += e0 * va0.w;
        ab.x += e0 * vb0.x; ab.y += e0 * vb0.y; ab.z += e0 * vb0.z; ab.w += e0 * vb0.w;
        aa.x += e1 * va1.x; aa.y += e1 * va1.y; aa.z += e1 * va1.z; aa.w += e1 * va1.w;
        ab.x += e1 * vb1.x; ab.y += e1 * vb1.y; ab.z += e1 * vb1.z; ab.w += e1 * vb1.w;
    }

    // fold across the 8 rr-groups (xor 4, 8, 16)
#pragma unroll
    for (int off = 4; off <= 16; off <<= 1) {
        aa.x += __shfl_xor_sync(0xffffffffu, aa.x, off);
        aa.y += __shfl_xor_sync(0xffffffffu, aa.y, off);
        aa.z += __shfl_xor_sync(0xffffffffu, aa.z, off);
        aa.w += __shfl_xor_sync(0xffffffffu, aa.w, off);
        ab.x += __shfl_xor_sync(0xffffffffu, ab.x, off);
        ab.y += __shfl_xor_sync(0xffffffffu, ab.y, off);
        ab.z += __shfl_xor_sync(0xffffffffu, ab.z, off);
        ab.w += __shfl_xor_sync(0xffffffffu, ab.w, off);
        l    += __shfl_xor_sync(0xffffffffu, l, off);
    }
    if (rr == 0) {
        float inv = 1.0f / l;
        float* dst = &g_O[(size_t)n * (K * S) + k * S + f2 * 8];
        *(float4*)&dst[0] = make_float4(aa.x * inv, aa.y * inv, aa.z * inv, aa.w * inv);
        *(float4*)&dst[4] = make_float4(ab.x * inv, ab.y * inv, ab.z * inv, ab.w * inv);
    }
}

// ================= O2 = (I - lam*L) @ O_cat =================
__global__ void k_lapO(const float* __restrict__ lambda_lap) {
    int n = blockIdx.x * 8 + (threadIdx.x >> 5);
    int lane = threadIdx.x & 31;
    const float4* O = (const float4*)g_O;
    const int* cols = g_col + (size_t)n * MAXDEG;
    int dn = g_deg[n];
    float4 o = O[(size_t)n * 32 + lane];
    float4 s = make_float4(0.f, 0.f, 0.f, 0.f);
    int c = 0;
    for (; c + 4 <= dn; c += 4) {
        float4 v0 = O[(size_t)cols[c] * 32 + lane];
        float4 v1 = O[(size_t)cols[c + 1] * 32 + lane];
        float4 v2 = O[(size_t)cols[c + 2] * 32 + lane];
        float4 v3 = O[(size_t)cols[c + 3] * 32 + lane];
        s.x += (v0.x + v1.x) + (v2.x + v3.x);
        s.y += (v0.y + v1.y) + (v2.y + v3.y);
        s.z += (v0.z + v1.z) + (v2.z + v3.z);
        s.w += (v0.w + v1.w) + (v2.w + v3.w);
    }
    for (; c < dn; c++) {
        float4 v = O[(size_t)cols[c] * 32 + lane];
        s.x += v.x; s.y += v.y; s.z += v.z; s.w += v.w;
    }
    float lam = lambda_lap[0];
    float fd = (float)dn;
    float4 r;
    r.x = o.x - lam * (fd * o.x - s.x);
    r.y = o.y - lam * (fd * o.y - s.y);
    r.z = o.z - lam * (fd * o.z - s.z);
    r.w = o.w - lam * (fd * o.w - s.w);
    ((float4*)g_O2)[(size_t)n * 32 + lane] = r;
}

// ================= H_out = softthresh(hops0 + ETA * O2 @ Wc) =================
__global__ void k_HoutG(const float* __restrict__ hops,
                        const float* __restrict__ threshold,
                        float* __restrict__ out) {
    __shared__ float as[32][33];
    __shared__ float ws[32][33];
    int n0 = blockIdx.x * 32, d0 = blockIdx.y * 32;
    int lane = threadIdx.x & 31;
    int row = threadIdx.x >> 5;
    float acc[4] = {0.f, 0.f, 0.f, 0.f};
    for (int cc = 0; cc < K * S; cc += 32) {
#pragma unroll
        for (int i = 0; i < 4; i++) {
            int r = row + i * 8;
            as[r][lane] = g_O2[(size_t)(n0 + r) * (K * S) + cc + lane];
            ws[r][lane] = g_Wc[(size_t)(cc + r) * D + d0 + lane];
        }
        __syncthreads();
#pragma unroll
        for (int dd = 0; dd < 32; dd++) {
            float wv = ws[dd][lane];
#pragma unroll
            for (int i = 0; i < 4; i++) acc[i] += as[row * 4 + i][dd] * wv;
        }
        __syncthreads();
    }
    float th = threshold[d0 + lane];
#pragma unroll
    for (int i = 0; i < 4; i++) {
        int n = n0 + row * 4 + i;
        float hh = hops[(size_t)n * D + d0 + lane] + ETA * acc[i];
        float ab = fabsf(hh) - th;
        out[(size_t)n * D + d0 + lane] = (ab > 0.f) ? copysignf(ab, hh) : 0.f;
    }
}

// ================= lap_smooth partials (symmetric half) + fused final =================
__global__ void k_lapF(const float* __restrict__ Hout, const float* __restrict__ hw,
                       float* __restrict__ out, int out_size) {
    __shared__ int hd[4];
    if (threadIdx.x < 4) {
        int nn = blockIdx.x * 4 + threadIdx.x;
        const int* cc = g_col + (size_t)nn * MAXDEG;
        int lo = 0, hi = g_deg[nn];
        while (lo < hi) {
            int mid = (lo + hi) >> 1;
            if (cc[mid] < nn) lo = mid + 1; else hi = mid;
        }
        hd[threadIdx.x] = lo;
    }
    __syncthreads();
    int g = threadIdx.x >> 6;
    int n = blockIdx.x * 4 + g;
    int t = threadIdx.x & 63;
    const float4* H = (const float4*)Hout;
    const int* cols = g_col + (size_t)n * MAXDEG;
    int dn = g_deg[n];
    int hn = hd[g];
    float4 h = H[(size_t)n * 64 + t];
    float4 vs = make_float4(0.f, 0.f, 0.f, 0.f);
    int c = 0;
    for (; c + 4 <= hn; c += 4) {
        float4 v0 = H[(size_t)cols[c] * 64 + t];
        float4 v1 = H[(size_t)cols[c + 1] * 64 + t];
        float4 v2 = H[(size_t)cols[c + 2] * 64 + t];
        float4 v3 = H[(size_t)cols[c + 3] * 64 + t];
        vs.x += (v0.x + v1.x) + (v2.x + v3.x);
        vs.y += (v0.y + v1.y) + (v2.y + v3.y);
        vs.z += (v0.z + v1.z) + (v2.z + v3.z);
        vs.w += (v0.w + v1.w) + (v2.w + v3.w);
    }
    for (; c < hn; c++) {
        float4 v = H[(size_t)cols[c] * 64 + t];
        vs.x += v.x; vs.y += v.y; vs.z += v.z; vs.w += v.w;
    }
    float fd = (float)dn - 1.0f;
    float dot = fd * (h.x * h.x + h.y * h.y + h.z * h.z + h.w * h.w)
              - 2.0f * (h.x * vs.x + h.y * vs.y + h.z * vs.z + h.w * vs.w);
    dot = warpSum(dot);
    __shared__ float sred[8];
    if ((threadIdx.x & 31) == 0) sred[threadIdx.x >> 5] = dot;
    __syncthreads();
    if (threadIdx.x < 4)
        g_partials[blockIdx.x * 4 + threadIdx.x] =
            sred[threadIdx.x * 2] + sred[threadIdx.x * 2 + 1];

    __threadfence();
    __shared__ int isLast;
    if (threadIdx.x == 0) {
        int v = atomicAdd(&g_ctr, 1);
        isLast = (v == (int)gridDim.x - 1) ? 1 : 0;
        if (isLast) atomicExch(&g_ctr, 0);
    }
    __syncthreads();
    if (!isLast) return;
    __threadfence();

    float v = 0.f;
    for (int i = threadIdx.x; i < N; i += 256) v += g_partials[i];
    __shared__ float red2[256];
    red2[threadIdx.x] = v;
    __syncthreads();
    for (int off = 128; off > 0; off >>= 1) {
        if (threadIdx.x < off) red2[threadIdx.x] += red2[threadIdx.x + off];
        __syncthreads();
    }
    if (threadIdx.x == 0) {
        float orth = 0.f;
        for (int p = 0; p < 10; p++) orth += g_orth[p];
        float m = fmaxf(fmaxf(hw[0], hw[1]), fmaxf(hw[2], hw[3]));
        float e0 = expf(hw[0] - m), e1 = expf(hw[1] - m);
        float e2 = expf(hw[2] - m), e3 = expf(hw[3] - m);
        float s = e0 + e1 + e2 + e3;
        int base = N * D;
        if (base < out_size) out[base] = orth;
        if (base + 1 < out_size) out[base + 1] = red2[0];
        if (base + 2 < out_size) out[base + 2] = e0 / s;
        if (base + 3 < out_size) out[base + 3] = e1 / s;
        if (base + 4 < out_size) out[base + 4] = e2 / s;
        if (base + 5 < out_size) out[base + 5] = e3 / s;
    }
}

// ---------------- launch ----------------
extern "C" void kernel_launch(void* const* d_in, const int* in_sizes, int n_in,
                              void* d_out, int out_size) {
    const float* hops      = (const float*)d_in[0];
    const float* adj       = (const float*)d_in[1];
    const float* U         = (const float*)d_in[3];
    const float* hw        = (const float*)d_in[4];
    const float* threshold = (const float*)d_in[5];
    const float* lam       = (const float*)d_in[6];
    float* out = (float*)d_out;

    k_mega1<<<810, 256>>>(hops, adj, U, hw);
    k_gram<<<128, 1024>>>();
    {
        dim3 g(N / 32, K);
        k_MZ<<<g, 256>>>();
    }
    k_attn<<<(K * N) / 8, 256>>>();
    k_lapO<<<N / 8, 256>>>(lam);
    {
        dim3 g(N / 32, D / 32);
        k_HoutG<<<g, 256>>>(hops, threshold, out);
    }
    k_lapF<<<N / 4, 256>>>(out, hw, out, out_size);
}